// round 13
// baseline (speedup 1.0000x reference)
#include <cuda_runtime.h>
#include <cuda_fp16.h>
#include <cstdint>

// ============================================================================
// Deformation net, HMMA fp16 single-pass (fp32 accum).
// CTA = 64 points, 128 threads (4 warps), 2 CTAs/SM, 255-reg budget.
// Warp w owns GEMM1 cols [w*64, w*64+64) (nt=8) x all 64 rows (mt=4).
//  -> 128 B of L1 traffic per MMA (was 192), 32 MMAs per A-load batch.
//  - A staged coalesced (32-row chunks), ReLU in pack, fp16 frags in smem.
//  - W1 pre-packed per-thread fp16 B-frag images; LDG.128 double-buffered.
//  - Heads 0-3 GEMM2: SIMT fp32 partials K-split over 4 warps -> red[h];
//    one combined reduce/output phase. Head 4 GEMM2 on HMMA.
// ============================================================================

#define DEVI __device__ __forceinline__

// W1 packed frags: [head][ks][slot 0..3][tid 0..127] x uint4 = 640KB
//  slot s holds nt-frags {2s, 2s+1} for thread tid (warp cols = w*64..+64).
__device__ __align__(16) unsigned char g_w1pk[5 * 16 * 4 * 128 * 16];
// W2 packed frags (head 4 uses slots 4..9): [slot][ks2][lane] x uint2
__device__ __align__(8) unsigned char g_w2pk[10 * 16 * 32 * 8];

DEVI uint32_t f2h2(float x, float y) {
    __half2 h = __floats2half2_rn(x, y);    // low = x, high = y
    return *(uint32_t*)&h;
}

__global__ void prep_all(const float* w10, const float* w11, const float* w12,
                         const float* w13, const float* w14,
                         const float* w20, const float* w21, const float* w22,
                         const float* w23, const float* w24) {
    int idx = blockIdx.x * blockDim.x + threadIdx.x;
    if (idx < 10240) {                 // 5 heads * 16 ks * 128 tid
        const float* ws[5] = {w10, w11, w12, w13, w14};
        int h = idx >> 11, ks = (idx >> 7) & 15, tid = idx & 127;
        int w = tid >> 5, lane = tid & 31;
        int gq = lane >> 2, cc = lane & 3;
        const float* W = ws[h];
        uint4* base = (uint4*)(g_w1pk + (size_t)(h * 16 + ks) * 8192);
#pragma unroll
        for (int s = 0; s < 4; s++) {
            uint32_t fr[4];
#pragma unroll
            for (int half = 0; half < 2; half++) {
                int ntl = 2 * s + half;
                int nn = w * 64 + ntl * 8 + gq;
                int k0 = ks * 16 + cc * 2;
                float v[4];
                int kk[4] = {k0, k0 + 1, k0 + 8, k0 + 9};
#pragma unroll
                for (int j = 0; j < 4; j++)
                    v[j] = (kk[j] < 255 && nn < 255) ? W[kk[j] * 255 + nn] : 0.0f;
                fr[half * 2 + 0] = f2h2(v[0], v[1]);
                fr[half * 2 + 1] = f2h2(v[2], v[3]);
            }
            base[s * 128 + tid] = make_uint4(fr[0], fr[1], fr[2], fr[3]);
        }
    } else if (idx < 10240 + 5120) {
        const float* ws[5] = {w20, w21, w22, w23, w24};
        const int ods[5] = {1, 3, 3, 4, 48};
        int j = idx - 10240;
        int slot = j >> 9, ks2 = (j >> 5) & 15, lane = j & 31;
        int head = (slot < 4) ? slot : 4;
        int nt2  = (slot < 4) ? 0 : slot - 4;
        int od = ods[head];
        const float* W = ws[head];
        int nn = nt2 * 8 + (lane >> 2);
        int k0 = ks2 * 16 + (lane & 3) * 2;
        float v[4];
        int kk[4] = {k0, k0 + 1, k0 + 8, k0 + 9};
#pragma unroll
        for (int q = 0; q < 4; q++)
            v[q] = (kk[q] < 255 && nn < od) ? W[kk[q] * od + nn] : 0.0f;
        ((uint2*)g_w2pk)[(slot * 16 + ks2) * 32 + lane] =
            make_uint2(f2h2(v[0], v[1]), f2h2(v[2], v[3]));
    }
}

DEVI void mma_f16(float* d, const uint32_t* a, uint32_t b0, uint32_t b1) {
    asm("mma.sync.aligned.m16n8k16.row.col.f32.f16.f16.f32 "
        "{%0,%1,%2,%3}, {%4,%5,%6,%7}, {%8,%9}, {%0,%1,%2,%3};"
        : "+f"(d[0]), "+f"(d[1]), "+f"(d[2]), "+f"(d[3])
        : "r"(a[0]), "r"(a[1]), "r"(a[2]), "r"(a[3]), "r"(b0), "r"(b1));
}

struct Params {
    const float* opa; const float* shs; const float* tim; const float* sem;
    const float* pnt; const float* scl; const float* rot; const float* dx;
    const float* w1[5]; const float* b1[5]; const float* w2[5]; const float* b2[5];
    float* out; int n;
};

// ---- smem layout (bytes), ~77 KB (2 CTAs/SM) ----------------------------------
#define OFF_APK   0                    // 16ks x 4mt x 32lane x 16B = 32768
#define OFF_SCR   32768                // staging 32x257 f32 (32896); later red[4]x4KB
#define OFF_W2S4  (OFF_SCR + 32896)
#define OFF_MASK  (OFF_W2S4 + 11264)
#define OFF_TPE   (OFF_MASK + 256)
#define SMEM_BYTES (OFF_TPE + 256)

DEVI uint32_t apk1(int ks, int mt, int lane) {
    return (uint32_t)(((ks * 4 + mt) * 32 + lane) * 16);
}

// ---- per-head SIMT GEMM2 partials (syncless): K-split over 4 warps ------------
template <int OD>
DEVI void part_g2(const float (*acc)[8][4], const float* b1r, const float* w2h,
                  float4* redh, int w, int gq, int cc) {
    float part[8][OD];
#pragma unroll
    for (int s = 0; s < 8; s++)
#pragma unroll
        for (int o = 0; o < OD; o++) part[s][o] = 0.0f;
#pragma unroll
    for (int nt = 0; nt < 8; nt++) {
        float wv[2][OD];
#pragma unroll
        for (int e1 = 0; e1 < 2; e1++) {
            int k = w * 64 + nt * 8 + cc * 2 + e1;
#pragma unroll
            for (int o = 0; o < OD; o++)
                wv[e1][o] = (k < 255) ? w2h[k * OD + o] : 0.0f;
        }
#pragma unroll
        for (int mt = 0; mt < 4; mt++)
#pragma unroll
            for (int e = 0; e < 4; e++) {
                float hv = fmaxf(acc[mt][nt][e] + b1r[nt * 2 + (e & 1)], 0.0f);
                int s = mt * 2 + (e >> 1);
#pragma unroll
                for (int o = 0; o < OD; o++)
                    part[s][o] += hv * wv[e & 1][o];
            }
    }
#pragma unroll
    for (int s = 0; s < 8; s++)
#pragma unroll
        for (int o = 0; o < OD; o++) {
            float v = part[s][o];
            v += __shfl_xor_sync(0xffffffffu, v, 1);
            v += __shfl_xor_sync(0xffffffffu, v, 2);
            part[s][o] = v;
        }
    if (cc == 0) {
#pragma unroll
        for (int s = 0; s < 8; s++) {
            int m = (s >> 1) * 16 + gq + (s & 1) * 8;
            redh[m * 4 + w] = make_float4(part[s][0],
                                          OD > 1 ? part[s][1] : 0.0f,
                                          OD > 2 ? part[s][2] : 0.0f,
                                          OD > 3 ? part[s][3] : 0.0f);
        }
    }
}

__global__ __launch_bounds__(128, 2)
void deform9(Params p) {
    extern __shared__ __align__(16) unsigned char sm[];
    float*  H1raw = (float*)(sm + OFF_SCR);     // 32 rows x stride 257
    float*  w2S4  = (float*)(sm + OFF_W2S4);
    float*  maskS = (float*)(sm + OFF_MASK);
    float*  tpeS  = (float*)(sm + OFF_TPE);

    const int tid = threadIdx.x, w = tid >> 5, lane = tid & 31;
    const int gq = lane >> 2, cc = lane & 3;
    const int n = p.n, g0 = blockIdx.x * 64;
    const int oSHS = 11 * n, oDSH = 62 * n;
    const int w2off[4] = {0, 256, 1024, 1792};
    const int ods4[4] = {1, 3, 3, 4};

    // prefetch B(h=0, ks=0) early
    uint4 cb[4];
    {
        const uint4* b = (const uint4*)g_w1pk;
#pragma unroll
        for (int i = 0; i < 4; i++) cb[i] = b[i * 128 + tid];
    }

    if (tid < 32) {
        float t = p.tim[0];
        float freq = exp2f((float)(2 * tid) * (13.287712379549449f / 32.0f));
        float a = t / freq;
        tpeS[2 * tid] = sinf(a);
        tpeS[2 * tid + 1] = cosf(a);
    }
#pragma unroll 1
    for (int hh = 0; hh < 4; hh++)
        for (int i = tid; i < 255 * ods4[hh]; i += 128)
            w2S4[w2off[hh] + i] = p.w2[hh][i];
    __syncthreads();

    // ---- build A (raw), two 32-row halves; pack fp16 frags into Apk --------
#pragma unroll 1
    for (int half = 0; half < 2; half++) {
        const int base = g0 + half * 32;
        if (base + 32 <= n) {
            const float4* sem4 = (const float4*)p.sem;
            const float4* shs4 = (const float4*)p.shs;
#pragma unroll 1
            for (int i = tid; i < 1024; i += 128) {      // sem: 32 x 128
                int r = i & 31, c = i >> 5;
                float4 v = sem4[(base + r) * 32 + c];
                float* d = H1raw + r * 257 + 59 + c * 4;
                d[0] = v.x; d[1] = v.y; d[2] = v.z; d[3] = v.w;
            }
#pragma unroll 1
            for (int i = tid; i < 384; i += 128) {       // shs: 32 x 48
                int r = i & 31, c = i >> 5;
                float4 v = shs4[(base + r) * 12 + c];
                float* d = H1raw + r * 257 + 11 + c * 4;
                d[0] = v.x; d[1] = v.y; d[2] = v.z; d[3] = v.w;
            }
#pragma unroll 1
            for (int i = tid; i < 416; i += 128) {       // pnt/rot/scl/dx: 13/row
                int r = i % 32, j = i / 32;
                int g = base + r;
                if (j < 3)       H1raw[r * 257 + j] = p.pnt[g * 3 + j];
                else if (j < 7)  H1raw[r * 257 + j] = p.rot[g * 4 + j - 3];
                else if (j < 10) H1raw[r * 257 + j] = p.scl[g * 3 + j - 7];
                else             H1raw[r * 257 + 177 + j] = p.dx[g * 3 + j - 10];
            }
            if (tid < 32) {
                int g = base + tid;
                H1raw[tid * 257 + 10]  = p.opa[g];
                H1raw[tid * 257 + 190] = p.tim[g];
                H1raw[tid * 257 + 255] = 0.0f;
            }
#pragma unroll 1
            for (int i = tid; i < 2048; i += 128) {      // tpe: 32 x 64
                int r = i & 31, j = i >> 5;
                H1raw[r * 257 + 191 + j] = tpeS[j];
            }
        } else {
            for (int idx = tid; idx < 32 * 256; idx += 128) {
                int lr = idx >> 8, k = idx & 255;
                int g = base + lr;
                float v = 0.0f;
                if (g < n && k < 255) {
                    if      (k < 3)    v = p.pnt[g * 3 + k];
                    else if (k < 7)    v = p.rot[g * 4 + (k - 3)];
                    else if (k < 10)   v = p.scl[g * 3 + (k - 7)];
                    else if (k == 10)  v = p.opa[g];
                    else if (k < 59)   v = p.shs[g * 48 + (k - 11)];
                    else if (k < 187)  v = p.sem[g * 128 + (k - 59)];
                    else if (k < 190)  v = p.dx[g * 3 + (k - 187)];
                    else if (k == 190) v = p.tim[g];
                    else               v = tpeS[k - 191];
                }
                H1raw[lr * 257 + k] = v;
            }
            if (tid < 32) H1raw[tid * 257 + 255] = 0.0f;
        }
        __syncthreads();
        // pack 32 frag-sets (ks 0..15, mtl 0..1), 8 per warp; relu here
#pragma unroll 1
        for (int j = 0; j < 8; j++) {
            int f = w * 8 + j;                 // 0..31 = ks*2 + mtl
            int ks = f >> 1, mtl = f & 1;
            int mt = half * 2 + mtl;
            int r0 = mtl * 16 + gq, r1 = r0 + 8;
            int k0 = ks * 16 + cc * 2;
            uint4 fr;
            fr.x = f2h2(fmaxf(H1raw[r0 * 257 + k0],     0.0f),
                        fmaxf(H1raw[r0 * 257 + k0 + 1], 0.0f));
            fr.y = f2h2(fmaxf(H1raw[r1 * 257 + k0],     0.0f),
                        fmaxf(H1raw[r1 * 257 + k0 + 1], 0.0f));
            fr.z = f2h2(fmaxf(H1raw[r0 * 257 + k0 + 8], 0.0f),
                        fmaxf(H1raw[r0 * 257 + k0 + 9], 0.0f));
            fr.w = f2h2(fmaxf(H1raw[r1 * 257 + k0 + 8], 0.0f),
                        fmaxf(H1raw[r1 * 257 + k0 + 9], 0.0f));
            *(uint4*)(sm + OFF_APK + apk1(ks, mt, lane)) = fr;
        }
        __syncthreads();
    }
    if (tid < 64) { int g = g0 + tid; if (g < n) p.out[10 * n + g] = p.opa[g]; }

#pragma unroll 1
    for (int h = 0; h < 5; h++) {
        float acc[4][8][4];
#pragma unroll
        for (int a = 0; a < 4; a++)
#pragma unroll
            for (int b = 0; b < 8; b++)
#pragma unroll
                for (int e = 0; e < 4; e++) acc[a][b][e] = 0.0f;

        // ---------- GEMM1 mainloop: mt=4 x nt=8, single fp16 pass, no syncs --
#pragma unroll 1
        for (int ks = 0; ks < 16; ks++) {
            uint4 nb[4];
            if (ks < 15) {
                const uint4* b = (const uint4*)(g_w1pk + (size_t)(h * 16 + ks + 1) * 8192);
#pragma unroll
                for (int i = 0; i < 4; i++) nb[i] = b[i * 128 + tid];
            }
            const uint32_t bf[8][2] = {
                {cb[0].x, cb[0].y}, {cb[0].z, cb[0].w},
                {cb[1].x, cb[1].y}, {cb[1].z, cb[1].w},
                {cb[2].x, cb[2].y}, {cb[2].z, cb[2].w},
                {cb[3].x, cb[3].y}, {cb[3].z, cb[3].w}};
#pragma unroll
            for (int mt = 0; mt < 4; mt++) {
                uint4 q = *(const uint4*)(sm + OFF_APK + apk1(ks, mt, lane));
                uint32_t A[4] = {q.x, q.y, q.z, q.w};
#pragma unroll
                for (int nt = 0; nt < 8; nt++)
                    mma_f16(acc[mt][nt], A, bf[nt][0], bf[nt][1]);
            }
            if (ks < 15) {
#pragma unroll
                for (int i = 0; i < 4; i++) cb[i] = nb[i];
            }
        }
        if (h < 4) {
            const uint4* b = (const uint4*)(g_w1pk + (size_t)((h + 1) * 16) * 8192);
#pragma unroll
            for (int i = 0; i < 4; i++) cb[i] = b[i * 128 + tid];
        }

        float b1r[16];
#pragma unroll
        for (int nt = 0; nt < 8; nt++)
#pragma unroll
            for (int e = 0; e < 2; e++) {
                int nn = w * 64 + nt * 8 + cc * 2 + e;
                b1r[nt * 2 + e] = (nn < 255) ? p.b1[h][nn] : 0.0f;
            }

        if (h < 4) {
            // ---------- SIMT partials -> red[h], NO sync ----------
            float4* redh = (float4*)(sm + OFF_SCR + h * 4096);
            if      (h == 0) part_g2<1>(acc, b1r, w2S4 + w2off[0], redh, w, gq, cc);
            else if (h == 3) part_g2<4>(acc, b1r, w2S4 + w2off[3], redh, w, gq, cc);
            else if (h == 1) part_g2<3>(acc, b1r, w2S4 + w2off[1], redh, w, gq, cc);
            else             part_g2<3>(acc, b1r, w2S4 + w2off[2], redh, w, gq, cc);
        } else {
            // ---------- head 4: pack H1 fp16 frags into Apk ----------
            __syncthreads();   // all warps done reading A frags
#pragma unroll
            for (int j = 0; j < 4; j++) {
                const int ks2 = 4 * w + j;   // warp's 64 cols = 4 k-windows
#pragma unroll
                for (int mt = 0; mt < 4; mt++) {
                    uint4 fr;
                    fr.x = f2h2(fmaxf(acc[mt][2 * j][0] + b1r[4 * j + 0], 0.0f),
                                fmaxf(acc[mt][2 * j][1] + b1r[4 * j + 1], 0.0f));
                    fr.y = f2h2(fmaxf(acc[mt][2 * j][2] + b1r[4 * j + 0], 0.0f),
                                fmaxf(acc[mt][2 * j][3] + b1r[4 * j + 1], 0.0f));
                    fr.z = f2h2(fmaxf(acc[mt][2 * j + 1][0] + b1r[4 * j + 2], 0.0f),
                                fmaxf(acc[mt][2 * j + 1][1] + b1r[4 * j + 3], 0.0f));
                    fr.w = f2h2(fmaxf(acc[mt][2 * j + 1][2] + b1r[4 * j + 2], 0.0f),
                                fmaxf(acc[mt][2 * j + 1][3] + b1r[4 * j + 3], 0.0f));
                    *(uint4*)(sm + OFF_APK + apk1(ks2, mt, lane)) = fr;
                }
            }
            __syncthreads();

            // ---------- combined: reduce heads 0-3 (warp = head) + mask ------
            {
                const int hh = w;
                const float4* rb = (const float4*)(sm + OFF_SCR + hh * 4096);
                float4 s4[2];
#pragma unroll
                for (int rep = 0; rep < 2; rep++) {
                    int m = lane + 32 * rep;
                    float4 a4 = make_float4(0.f, 0.f, 0.f, 0.f);
#pragma unroll
                    for (int wi = 0; wi < 4; wi++) {
                        float4 r = rb[m * 4 + wi];
                        a4.x += r.x; a4.y += r.y; a4.z += r.z; a4.w += r.w;
                    }
                    s4[rep] = a4;
                    if (hh == 0)
                        maskS[m] = 1.0f / (1.0f + expf(-(a4.x + p.b2[0][0])));
                }
                __syncthreads();    // maskS visible
#pragma unroll
                for (int rep = 0; rep < 2; rep++) {
                    int m = lane + 32 * rep;
                    int g = g0 + m;
                    if (hh >= 1 && g < n) {
                        float mk = maskS[m];
                        float vo[4] = {s4[rep].x, s4[rep].y, s4[rep].z, s4[rep].w};
                        if (hh == 1) {
#pragma unroll
                            for (int o = 0; o < 3; o++) {
                                float val = vo[o] + p.b2[1][o];
                                p.out[59 * n + g * 3 + o] = val;                 // dx_out
                                p.out[g * 3 + o] = p.pnt[g * 3 + o] + val * mk;  // pts
                            }
                        } else if (hh == 2) {
#pragma unroll
                            for (int o = 0; o < 3; o++) {
                                float val = vo[o] + p.b2[2][o];
                                p.out[3 * n + g * 3 + o] = p.scl[g * 3 + o] + val * mk;
                            }
                        } else {
#pragma unroll
                            for (int o = 0; o < 4; o++) {
                                float val = vo[o] + p.b2[3][o];
                                p.out[6 * n + g * 4 + o] = p.rot[g * 4 + o] + val * mk;
                            }
                        }
                    }
                }
            }

            // ---------- head 4 GEMM2 on HMMA: 24 jobs over 4 warps ----------
#pragma unroll 1
            for (int jb = 0; jb < 6; jb++) {
                int t = w + 4 * jb;            // 0..23
                int mt = t / 6, nt2 = t % 6;
                float d0[4] = {0, 0, 0, 0};
                const uint2* wb = (const uint2*)g_w2pk + (4 + nt2) * 16 * 32;
                uint2 B = wb[lane];
#pragma unroll 1
                for (int ks2 = 0; ks2 < 16; ks2++) {
                    uint2 Bn;
                    if (ks2 < 15) Bn = wb[(ks2 + 1) * 32 + lane];
                    uint4 ah4 = *(const uint4*)(sm + OFF_APK + apk1(ks2, mt, lane));
                    uint32_t ah[4] = {ah4.x, ah4.y, ah4.z, ah4.w};
                    mma_f16(d0, ah, B.x, B.y);
                    if (ks2 < 15) B = Bn;
                }
#pragma unroll
                for (int e = 0; e < 4; e++) {
                    int o = nt2 * 8 + cc * 2 + (e & 1);
                    int m = mt * 16 + gq + ((e >> 1) << 3);
                    int g = g0 + m;
                    if (g < n) {
                        float val = d0[e] + p.b2[4][o];
                        float mk = maskS[m];
                        p.out[oDSH + g * 48 + o] = val;
                        p.out[oSHS + g * 48 + o] = p.shs[g * 48 + o] + val * mk;
                    }
                }
            }
        }
    }
}

extern "C" void kernel_launch(void* const* d_in, const int* in_sizes, int n_in,
                              void* d_out, int out_size) {
    Params p;
    p.opa = (const float*)d_in[0];
    p.shs = (const float*)d_in[1];
    p.tim = (const float*)d_in[2];
    p.sem = (const float*)d_in[3];
    p.pnt = (const float*)d_in[4];
    p.scl = (const float*)d_in[5];
    p.rot = (const float*)d_in[6];
    p.dx  = (const float*)d_in[7];
    for (int h = 0; h < 5; h++) {
        p.w1[h] = (const float*)d_in[8 + h * 4 + 0];
        p.b1[h] = (const float*)d_in[8 + h * 4 + 1];
        p.w2[h] = (const float*)d_in[8 + h * 4 + 2];
        p.b2[h] = (const float*)d_in[8 + h * 4 + 3];
    }
    p.out = (float*)d_out;
    p.n   = in_sizes[0];

    prep_all<<<60, 256>>>(p.w1[0], p.w1[1], p.w1[2], p.w1[3], p.w1[4],
                          p.w2[0], p.w2[1], p.w2[2], p.w2[3], p.w2[4]);

    cudaFuncSetAttribute(deform9, cudaFuncAttributeMaxDynamicSharedMemorySize, SMEM_BYTES);
    const int grid = (p.n + 63) / 64;   // 3125
    deform9<<<grid, 128, SMEM_BYTES>>>(p);
}

// round 14
// speedup vs baseline: 1.5475x; 1.5475x over previous
#include <cuda_runtime.h>
#include <cuda_fp16.h>
#include <cstdint>

// ============================================================================
// Deformation net, HMMA fp16 single-pass (fp32 accum).
// CTA = 32 points, 128 threads (4 warps), 4 CTAs/SM.
// Warp w owns GEMM1 cols [w*64, w*64+64) (nt=8), mt=2 (rows 0..31).
//  - A staged coalesced, ReLU in pack, fp16 frags in smem (16KB).
//  - W1 pre-packed fp16 B-frag images; ks-loop unrolled x2 ping-pong (no MOVs).
//  - ALL GEMM2 on HMMA: per head, pack H1 frags into H1pk (16KB, reuses
//    staging region) then a 16-MMA chain. Heads 0-3: warps 0-1 (warps 2-3
//    run ahead into next mainloop). Head 4: 12 jobs over 4 warps.
// ============================================================================

#define DEVI __device__ __forceinline__

// W1 packed frags: [head][ks][slot 0..3][tid 0..127] x uint4 = 640KB
__device__ __align__(16) unsigned char g_w1pk[5 * 16 * 4 * 128 * 16];
// W2 packed frags: slots 0..3 = heads 0..3 (nt2=0); 4..9 = head4 nt2 0..5
__device__ __align__(8) unsigned char g_w2pk[10 * 16 * 32 * 8];

DEVI uint32_t f2h2(float x, float y) {
    __half2 h = __floats2half2_rn(x, y);
    return *(uint32_t*)&h;
}

__global__ void prep_all(const float* w10, const float* w11, const float* w12,
                         const float* w13, const float* w14,
                         const float* w20, const float* w21, const float* w22,
                         const float* w23, const float* w24) {
    int idx = blockIdx.x * blockDim.x + threadIdx.x;
    if (idx < 10240) {                 // 5 heads * 16 ks * 128 tid
        const float* ws[5] = {w10, w11, w12, w13, w14};
        int h = idx >> 11, ks = (idx >> 7) & 15, tid = idx & 127;
        int w = tid >> 5, lane = tid & 31;
        int gq = lane >> 2, cc = lane & 3;
        const float* W = ws[h];
        uint4* base = (uint4*)(g_w1pk + (size_t)(h * 16 + ks) * 8192);
#pragma unroll
        for (int s = 0; s < 4; s++) {
            uint32_t fr[4];
#pragma unroll
            for (int half = 0; half < 2; half++) {
                int ntl = 2 * s + half;
                int nn = w * 64 + ntl * 8 + gq;
                int k0 = ks * 16 + cc * 2;
                float v[4];
                int kk[4] = {k0, k0 + 1, k0 + 8, k0 + 9};
#pragma unroll
                for (int j = 0; j < 4; j++)
                    v[j] = (kk[j] < 255 && nn < 255) ? W[kk[j] * 255 + nn] : 0.0f;
                fr[half * 2 + 0] = f2h2(v[0], v[1]);
                fr[half * 2 + 1] = f2h2(v[2], v[3]);
            }
            base[s * 128 + tid] = make_uint4(fr[0], fr[1], fr[2], fr[3]);
        }
    } else if (idx < 10240 + 5120) {
        const float* ws[5] = {w20, w21, w22, w23, w24};
        const int ods[5] = {1, 3, 3, 4, 48};
        int j = idx - 10240;
        int slot = j >> 9, ks2 = (j >> 5) & 15, lane = j & 31;
        int head = (slot < 4) ? slot : 4;
        int nt2  = (slot < 4) ? 0 : slot - 4;
        int od = ods[head];
        const float* W = ws[head];
        int nn = nt2 * 8 + (lane >> 2);
        int k0 = ks2 * 16 + (lane & 3) * 2;
        float v[4];
        int kk[4] = {k0, k0 + 1, k0 + 8, k0 + 9};
#pragma unroll
        for (int q = 0; q < 4; q++)
            v[q] = (kk[q] < 255 && nn < od) ? W[kk[q] * od + nn] : 0.0f;
        ((uint2*)g_w2pk)[(slot * 16 + ks2) * 32 + lane] =
            make_uint2(f2h2(v[0], v[1]), f2h2(v[2], v[3]));
    }
}

DEVI void mma_f16(float* d, const uint32_t* a, uint32_t b0, uint32_t b1) {
    asm("mma.sync.aligned.m16n8k16.row.col.f32.f16.f16.f32 "
        "{%0,%1,%2,%3}, {%4,%5,%6,%7}, {%8,%9}, {%0,%1,%2,%3};"
        : "+f"(d[0]), "+f"(d[1]), "+f"(d[2]), "+f"(d[3])
        : "r"(a[0]), "r"(a[1]), "r"(a[2]), "r"(a[3]), "r"(b0), "r"(b1));
}

struct Params {
    const float* opa; const float* shs; const float* tim; const float* sem;
    const float* pnt; const float* scl; const float* rot; const float* dx;
    const float* w1[5]; const float* b1[5]; const float* w2[5]; const float* b2[5];
    float* out; int n;
};

// ---- smem layout (bytes), ~33.3 KB (4 CTAs/SM) --------------------------------
#define OFF_APK   0                    // 16ks x 2mt x 32lane x 16B = 16384
#define OFF_SCR   16384                // staging 16x257 f32 (16448); later H1pk 16384
#define OFF_MASK  (OFF_SCR + 16448)
#define OFF_TPE   (OFF_MASK + 128)
#define SMEM_BYTES (OFF_TPE + 256)

DEVI uint32_t apk1(int ks, int mt, int lane) {
    return (uint32_t)(((ks * 2 + mt) * 32 + lane) * 16);
}

#define MMA_BLOCK(BUF, KS)                                                     \
    do {                                                                       \
        const uint32_t bf[8][2] = {                                            \
            {BUF[0].x, BUF[0].y}, {BUF[0].z, BUF[0].w},                        \
            {BUF[1].x, BUF[1].y}, {BUF[1].z, BUF[1].w},                        \
            {BUF[2].x, BUF[2].y}, {BUF[2].z, BUF[2].w},                        \
            {BUF[3].x, BUF[3].y}, {BUF[3].z, BUF[3].w}};                       \
        _Pragma("unroll")                                                      \
        for (int mt = 0; mt < 2; mt++) {                                       \
            uint4 q = *(const uint4*)(sm + OFF_APK + apk1((KS), mt, lane));    \
            uint32_t A[4] = {q.x, q.y, q.z, q.w};                              \
            _Pragma("unroll")                                                  \
            for (int nt = 0; nt < 8; nt++)                                     \
                mma_f16(acc[mt][nt], A, bf[nt][0], bf[nt][1]);                 \
        }                                                                      \
    } while (0)

__global__ __launch_bounds__(128, 4)
void deform10(Params p) {
    extern __shared__ __align__(16) unsigned char sm[];
    float*  H1raw = (float*)(sm + OFF_SCR);     // 16 rows x stride 257
    float*  maskS = (float*)(sm + OFF_MASK);
    float*  tpeS  = (float*)(sm + OFF_TPE);

    const int tid = threadIdx.x, w = tid >> 5, lane = tid & 31;
    const int gq = lane >> 2, cc = lane & 3;
    const int n = p.n, g0 = blockIdx.x * 32;
    const int oSHS = 11 * n, oDSH = 62 * n;

    // prefetch B(h=0, ks=0)
    uint4 cb[4];
    {
        const uint4* b = (const uint4*)g_w1pk;
#pragma unroll
        for (int i = 0; i < 4; i++) cb[i] = b[i * 128 + tid];
    }

    if (tid < 32) {
        float t = p.tim[0];
        float freq = exp2f((float)(2 * tid) * (13.287712379549449f / 32.0f));
        float a = t / freq;
        tpeS[2 * tid] = sinf(a);
        tpeS[2 * tid + 1] = cosf(a);
    }
    __syncthreads();

    // ---- build A (raw), two 16-row chunks; pack fp16 frags into Apk --------
#pragma unroll 1
    for (int half = 0; half < 2; half++) {
        const int base = g0 + half * 16;
        if (base + 16 <= n) {
            const float4* sem4 = (const float4*)p.sem;
            const float4* shs4 = (const float4*)p.shs;
#pragma unroll 1
            for (int i = tid; i < 512; i += 128) {       // sem: 16 x 128
                int r = i & 15, c = i >> 4;
                float4 v = sem4[(base + r) * 32 + c];
                float* d = H1raw + r * 257 + 59 + c * 4;
                d[0] = v.x; d[1] = v.y; d[2] = v.z; d[3] = v.w;
            }
#pragma unroll 1
            for (int i = tid; i < 192; i += 128) {       // shs: 16 x 48
                int r = i & 15, c = i >> 4;
                float4 v = shs4[(base + r) * 12 + c];
                float* d = H1raw + r * 257 + 11 + c * 4;
                d[0] = v.x; d[1] = v.y; d[2] = v.z; d[3] = v.w;
            }
#pragma unroll 1
            for (int i = tid; i < 208; i += 128) {       // pnt/rot/scl/dx
                int r = i & 15, j = i >> 4;
                int g = base + r;
                if (j < 3)       H1raw[r * 257 + j] = p.pnt[g * 3 + j];
                else if (j < 7)  H1raw[r * 257 + j] = p.rot[g * 4 + j - 3];
                else if (j < 10) H1raw[r * 257 + j] = p.scl[g * 3 + j - 7];
                else             H1raw[r * 257 + 177 + j] = p.dx[g * 3 + j - 10];
            }
            if (tid < 16) {
                int g = base + tid;
                H1raw[tid * 257 + 10]  = p.opa[g];
                H1raw[tid * 257 + 190] = p.tim[g];
                H1raw[tid * 257 + 255] = 0.0f;
            }
#pragma unroll 1
            for (int i = tid; i < 1024; i += 128) {      // tpe: 16 x 64
                int r = i & 15, j = i >> 4;
                H1raw[r * 257 + 191 + j] = tpeS[j];
            }
        } else {
            for (int idx = tid; idx < 16 * 256; idx += 128) {
                int lr = idx >> 8, k = idx & 255;
                int g = base + lr;
                float v = 0.0f;
                if (g < n && k < 255) {
                    if      (k < 3)    v = p.pnt[g * 3 + k];
                    else if (k < 7)    v = p.rot[g * 4 + (k - 3)];
                    else if (k < 10)   v = p.scl[g * 3 + (k - 7)];
                    else if (k == 10)  v = p.opa[g];
                    else if (k < 59)   v = p.shs[g * 48 + (k - 11)];
                    else if (k < 187)  v = p.sem[g * 128 + (k - 59)];
                    else if (k < 190)  v = p.dx[g * 3 + (k - 187)];
                    else if (k == 190) v = p.tim[g];
                    else               v = tpeS[k - 191];
                }
                H1raw[lr * 257 + k] = v;
            }
            if (tid < 16) H1raw[tid * 257 + 255] = 0.0f;
        }
        __syncthreads();
#pragma unroll 1
        for (int j = 0; j < 4; j++) {
            int ks = w * 4 + j;
            int r0 = gq, r1 = gq + 8;
            int k0 = ks * 16 + cc * 2;
            uint4 fr;
            fr.x = f2h2(fmaxf(H1raw[r0 * 257 + k0],     0.0f),
                        fmaxf(H1raw[r0 * 257 + k0 + 1], 0.0f));
            fr.y = f2h2(fmaxf(H1raw[r1 * 257 + k0],     0.0f),
                        fmaxf(H1raw[r1 * 257 + k0 + 1], 0.0f));
            fr.z = f2h2(fmaxf(H1raw[r0 * 257 + k0 + 8], 0.0f),
                        fmaxf(H1raw[r0 * 257 + k0 + 9], 0.0f));
            fr.w = f2h2(fmaxf(H1raw[r1 * 257 + k0 + 8], 0.0f),
                        fmaxf(H1raw[r1 * 257 + k0 + 9], 0.0f));
            *(uint4*)(sm + OFF_APK + apk1(ks, half, lane)) = fr;
        }
        __syncthreads();
    }
    if (tid < 32) { int g = g0 + tid; if (g < n) p.out[10 * n + g] = p.opa[g]; }

#pragma unroll 1
    for (int h = 0; h < 5; h++) {
        float acc[2][8][4];
#pragma unroll
        for (int a = 0; a < 2; a++)
#pragma unroll
            for (int b = 0; b < 8; b++)
#pragma unroll
                for (int e = 0; e < 4; e++) acc[a][b][e] = 0.0f;

        // ---------- GEMM1 mainloop: unrolled x2 ping-pong, no syncs ----------
        const unsigned char* hbase = g_w1pk + (size_t)(h * 16) * 8192;
#pragma unroll 1
        for (int ks = 0; ks < 16; ks += 2) {
            uint4 nb[4];
            {
                const uint4* b = (const uint4*)(hbase + (size_t)(ks + 1) * 8192);
#pragma unroll
                for (int i = 0; i < 4; i++) nb[i] = b[i * 128 + tid];
            }
            MMA_BLOCK(cb, ks);
            if (ks < 14) {
                const uint4* b = (const uint4*)(hbase + (size_t)(ks + 2) * 8192);
#pragma unroll
                for (int i = 0; i < 4; i++) cb[i] = b[i * 128 + tid];
            } else if (h < 4) {
                const uint4* b = (const uint4*)(g_w1pk + (size_t)((h + 1) * 16) * 8192);
#pragma unroll
                for (int i = 0; i < 4; i++) cb[i] = b[i * 128 + tid];
            }
            MMA_BLOCK(nb, ks + 1);
        }

        // b1 for this warp's n-slice
        float b1r[16];
#pragma unroll
        for (int nt = 0; nt < 8; nt++)
#pragma unroll
            for (int e = 0; e < 2; e++) {
                int nn = w * 64 + nt * 8 + cc * 2 + e;
                b1r[nt * 2 + e] = (nn < 255) ? p.b1[h][nn] : 0.0f;
            }

        // ---------- pack H1 fp16 frags into H1pk (SCR region) ----------
        __syncthreads();   // previous GEMM2 readers of H1pk done
#pragma unroll
        for (int j = 0; j < 4; j++) {
            const int ks2 = 4 * w + j;       // warp's 64 cols = 4 k-windows
#pragma unroll
            for (int mt = 0; mt < 2; mt++) {
                uint4 fr;
                fr.x = f2h2(fmaxf(acc[mt][2 * j][0] + b1r[4 * j + 0], 0.0f),
                            fmaxf(acc[mt][2 * j][1] + b1r[4 * j + 1], 0.0f));
                fr.y = f2h2(fmaxf(acc[mt][2 * j][2] + b1r[4 * j + 0], 0.0f),
                            fmaxf(acc[mt][2 * j][3] + b1r[4 * j + 1], 0.0f));
                fr.z = f2h2(fmaxf(acc[mt][2 * j + 1][0] + b1r[4 * j + 2], 0.0f),
                            fmaxf(acc[mt][2 * j + 1][1] + b1r[4 * j + 3], 0.0f));
                fr.w = f2h2(fmaxf(acc[mt][2 * j + 1][2] + b1r[4 * j + 2], 0.0f),
                            fmaxf(acc[mt][2 * j + 1][3] + b1r[4 * j + 3], 0.0f));
                *(uint4*)(sm + OFF_SCR + apk1(ks2, mt, lane)) = fr;
            }
        }
        __syncthreads();   // H1pk visible to all warps

        // ---------- GEMM2 on HMMA + epilogue ----------
        if (h < 4) {
            const int od = (h == 3) ? 4 : ((h == 0) ? 1 : 3);
            if (w < 2) {
                const int mt = w;            // rows mt*16 .. +16
                float d0[4] = {0, 0, 0, 0};
                const uint2* wb = (const uint2*)g_w2pk + h * 16 * 32;
                uint2 B = wb[lane];
#pragma unroll 1
                for (int ks2 = 0; ks2 < 16; ks2++) {
                    uint2 Bn;
                    if (ks2 < 15) Bn = wb[(ks2 + 1) * 32 + lane];
                    uint4 ah4 = *(const uint4*)(sm + OFF_SCR + apk1(ks2, mt, lane));
                    uint32_t ah[4] = {ah4.x, ah4.y, ah4.z, ah4.w};
                    mma_f16(d0, ah, B.x, B.y);
                    if (ks2 < 15) B = Bn;
                }
                if (h == 0) {
                    if (cc == 0) {
                        float b20 = p.b2[0][0];
                        maskS[mt * 16 + gq]     = 1.0f / (1.0f + expf(-(d0[0] + b20)));
                        maskS[mt * 16 + gq + 8] = 1.0f / (1.0f + expf(-(d0[2] + b20)));
                    }
                } else {
#pragma unroll
                    for (int e = 0; e < 4; e++) {
                        int o = cc * 2 + (e & 1);
                        if (o < od) {
                            int m = mt * 16 + gq + ((e >> 1) << 3);
                            int g = g0 + m;
                            if (g < n) {
                                float val = d0[e] + p.b2[h][o];
                                float mk = maskS[m];   // same-warp producer
                                if (h == 1) {
                                    p.out[59 * n + g * 3 + o] = val;
                                    p.out[g * 3 + o] = p.pnt[g * 3 + o] + val * mk;
                                } else if (h == 2) {
                                    p.out[3 * n + g * 3 + o] = p.scl[g * 3 + o] + val * mk;
                                } else {
                                    p.out[6 * n + g * 4 + o] = p.rot[g * 4 + o] + val * mk;
                                }
                            }
                        }
                    }
                }
            }
            // warps 2-3 (and 0-1 after their job) fall through to next head's
            // mainloop; the pre-pack sync of head h+1 fences H1pk reuse.
        } else {
            // head 4: 12 jobs (2mt x 6nt2) over 4 warps
#pragma unroll 1
            for (int jb = 0; jb < 3; jb++) {
                int t = w + 4 * jb;            // 0..11
                int mt = t / 6, nt2 = t % 6;
                float d0[4] = {0, 0, 0, 0};
                const uint2* wb = (const uint2*)g_w2pk + (4 + nt2) * 16 * 32;
                uint2 B = wb[lane];
#pragma unroll 1
                for (int ks2 = 0; ks2 < 16; ks2++) {
                    uint2 Bn;
                    if (ks2 < 15) Bn = wb[(ks2 + 1) * 32 + lane];
                    uint4 ah4 = *(const uint4*)(sm + OFF_SCR + apk1(ks2, mt, lane));
                    uint32_t ah[4] = {ah4.x, ah4.y, ah4.z, ah4.w};
                    mma_f16(d0, ah, B.x, B.y);
                    if (ks2 < 15) B = Bn;
                }
#pragma unroll
                for (int e = 0; e < 4; e++) {
                    int o = nt2 * 8 + cc * 2 + (e & 1);
                    int m = mt * 16 + gq + ((e >> 1) << 3);
                    int g = g0 + m;
                    if (g < n) {
                        float val = d0[e] + p.b2[4][o];
                        float mk = maskS[m];
                        p.out[oDSH + g * 48 + o] = val;
                        p.out[oSHS + g * 48 + o] = p.shs[g * 48 + o] + val * mk;
                    }
                }
            }
        }
    }
}

extern "C" void kernel_launch(void* const* d_in, const int* in_sizes, int n_in,
                              void* d_out, int out_size) {
    Params p;
    p.opa = (const float*)d_in[0];
    p.shs = (const float*)d_in[1];
    p.tim = (const float*)d_in[2];
    p.sem = (const float*)d_in[3];
    p.pnt = (const float*)d_in[4];
    p.scl = (const float*)d_in[5];
    p.rot = (const float*)d_in[6];
    p.dx  = (const float*)d_in[7];
    for (int h = 0; h < 5; h++) {
        p.w1[h] = (const float*)d_in[8 + h * 4 + 0];
        p.b1[h] = (const float*)d_in[8 + h * 4 + 1];
        p.w2[h] = (const float*)d_in[8 + h * 4 + 2];
        p.b2[h] = (const float*)d_in[8 + h * 4 + 3];
    }
    p.out = (float*)d_out;
    p.n   = in_sizes[0];

    prep_all<<<60, 256>>>(p.w1[0], p.w1[1], p.w1[2], p.w1[3], p.w1[4],
                          p.w2[0], p.w2[1], p.w2[2], p.w2[3], p.w2[4]);

    cudaFuncSetAttribute(deform10, cudaFuncAttributeMaxDynamicSharedMemorySize, SMEM_BYTES);
    const int grid = (p.n + 31) / 32;   // 6250
    deform10<<<grid, 128, SMEM_BYTES>>>(p);
}

// round 15
// speedup vs baseline: 1.9166x; 1.2385x over previous
#include <cuda_runtime.h>
#include <cuda_fp16.h>
#include <cstdint>

// ============================================================================
// Deformation net, HMMA fp16 single-pass (fp32 accum).
// CTA = 32 points, 128 threads (4 warps), 4 CTAs/SM.
// Warp w owns GEMM1 cols [w*64, w*64+64) (nt=8), mt=2 (rows 0..31).
//  - GEMM1: ks-loop unrolled x2 ping-pong, B via LDG.128, no syncs.
//  - Heads 0-3 GEMM2: IN-REGISTER HMMA partials (C-frag == A-frag layout),
//    syncless D-partial dump to red[h]; one combined reduce/output phase.
//  - Head 4 GEMM2: H1 packed into dead A-frag region, 12 HMMA jobs.
// ============================================================================

#define DEVI __device__ __forceinline__

// W1 packed frags: [head][ks][slot 0..3][tid 0..127] x uint4 = 640KB
__device__ __align__(16) unsigned char g_w1pk[5 * 16 * 4 * 128 * 16];
// W2 packed frags: slots 0..3 = heads 0..3 (nt2=0); 4..9 = head4 nt2 0..5
__device__ __align__(8) unsigned char g_w2pk[10 * 16 * 32 * 8];

DEVI uint32_t f2h2(float x, float y) {
    __half2 h = __floats2half2_rn(x, y);
    return *(uint32_t*)&h;
}

__global__ void prep_all(const float* w10, const float* w11, const float* w12,
                         const float* w13, const float* w14,
                         const float* w20, const float* w21, const float* w22,
                         const float* w23, const float* w24) {
    int idx = blockIdx.x * blockDim.x + threadIdx.x;
    if (idx < 10240) {                 // 5 heads * 16 ks * 128 tid
        const float* ws[5] = {w10, w11, w12, w13, w14};
        int h = idx >> 11, ks = (idx >> 7) & 15, tid = idx & 127;
        int w = tid >> 5, lane = tid & 31;
        int gq = lane >> 2, cc = lane & 3;
        const float* W = ws[h];
        uint4* base = (uint4*)(g_w1pk + (size_t)(h * 16 + ks) * 8192);
#pragma unroll
        for (int s = 0; s < 4; s++) {
            uint32_t fr[4];
#pragma unroll
            for (int half = 0; half < 2; half++) {
                int ntl = 2 * s + half;
                int nn = w * 64 + ntl * 8 + gq;
                int k0 = ks * 16 + cc * 2;
                float v[4];
                int kk[4] = {k0, k0 + 1, k0 + 8, k0 + 9};
#pragma unroll
                for (int j = 0; j < 4; j++)
                    v[j] = (kk[j] < 255 && nn < 255) ? W[kk[j] * 255 + nn] : 0.0f;
                fr[half * 2 + 0] = f2h2(v[0], v[1]);
                fr[half * 2 + 1] = f2h2(v[2], v[3]);
            }
            base[s * 128 + tid] = make_uint4(fr[0], fr[1], fr[2], fr[3]);
        }
    } else if (idx < 10240 + 5120) {
        const float* ws[5] = {w20, w21, w22, w23, w24};
        const int ods[5] = {1, 3, 3, 4, 48};
        int j = idx - 10240;
        int slot = j >> 9, ks2 = (j >> 5) & 15, lane = j & 31;
        int head = (slot < 4) ? slot : 4;
        int nt2  = (slot < 4) ? 0 : slot - 4;
        int od = ods[head];
        const float* W = ws[head];
        int nn = nt2 * 8 + (lane >> 2);
        int k0 = ks2 * 16 + (lane & 3) * 2;
        float v[4];
        int kk[4] = {k0, k0 + 1, k0 + 8, k0 + 9};
#pragma unroll
        for (int q = 0; q < 4; q++)
            v[q] = (kk[q] < 255 && nn < od) ? W[kk[q] * od + nn] : 0.0f;
        ((uint2*)g_w2pk)[(slot * 16 + ks2) * 32 + lane] =
            make_uint2(f2h2(v[0], v[1]), f2h2(v[2], v[3]));
    }
}

DEVI void mma_f16(float* d, const uint32_t* a, uint32_t b0, uint32_t b1) {
    asm("mma.sync.aligned.m16n8k16.row.col.f32.f16.f16.f32 "
        "{%0,%1,%2,%3}, {%4,%5,%6,%7}, {%8,%9}, {%0,%1,%2,%3};"
        : "+f"(d[0]), "+f"(d[1]), "+f"(d[2]), "+f"(d[3])
        : "r"(a[0]), "r"(a[1]), "r"(a[2]), "r"(a[3]), "r"(b0), "r"(b1));
}

struct Params {
    const float* opa; const float* shs; const float* tim; const float* sem;
    const float* pnt; const float* scl; const float* rot; const float* dx;
    const float* w1[5]; const float* b1[5]; const float* w2[5]; const float* b2[5];
    float* out; int n;
};

// ---- smem layout (bytes), ~33.3 KB (4 CTAs/SM) --------------------------------
// APK: A frags (GEMM1); H1pk frags (head4 GEMM2).   16384
// SCR: staging 16x257 f32 (16448); later red[4] x 4KB D-partials.
#define OFF_APK   0
#define OFF_SCR   16384
#define OFF_MASK  (OFF_SCR + 16448)
#define OFF_TPE   (OFF_MASK + 128)
#define SMEM_BYTES (OFF_TPE + 256)

DEVI uint32_t apk1(int ks, int mt, int lane) {
    return (uint32_t)(((ks * 2 + mt) * 32 + lane) * 16);
}

#define MMA_BLOCK(BUF, KS)                                                     \
    do {                                                                       \
        const uint32_t bf[8][2] = {                                            \
            {BUF[0].x, BUF[0].y}, {BUF[0].z, BUF[0].w},                        \
            {BUF[1].x, BUF[1].y}, {BUF[1].z, BUF[1].w},                        \
            {BUF[2].x, BUF[2].y}, {BUF[2].z, BUF[2].w},                        \
            {BUF[3].x, BUF[3].y}, {BUF[3].z, BUF[3].w}};                       \
        _Pragma("unroll")                                                      \
        for (int mt = 0; mt < 2; mt++) {                                       \
            uint4 q = *(const uint4*)(sm + OFF_APK + apk1((KS), mt, lane));    \
            uint32_t A[4] = {q.x, q.y, q.z, q.w};                              \
            _Pragma("unroll")                                                  \
            for (int nt = 0; nt < 8; nt++)                                     \
                mma_f16(acc[mt][nt], A, bf[nt][0], bf[nt][1]);                 \
        }                                                                      \
    } while (0)

__global__ __launch_bounds__(128, 4)
void deform11(Params p) {
    extern __shared__ __align__(16) unsigned char sm[];
    float*  H1raw = (float*)(sm + OFF_SCR);     // 16 rows x stride 257
    float*  maskS = (float*)(sm + OFF_MASK);
    float*  tpeS  = (float*)(sm + OFF_TPE);

    const int tid = threadIdx.x, w = tid >> 5, lane = tid & 31;
    const int gq = lane >> 2, cc = lane & 3;
    const int n = p.n, g0 = blockIdx.x * 32;
    const int oSHS = 11 * n, oDSH = 62 * n;

    // prefetch B(h=0, ks=0)
    uint4 cb[4];
    {
        const uint4* b = (const uint4*)g_w1pk;
#pragma unroll
        for (int i = 0; i < 4; i++) cb[i] = b[i * 128 + tid];
    }

    if (tid < 32) {
        float t = p.tim[0];
        float freq = exp2f((float)(2 * tid) * (13.287712379549449f / 32.0f));
        float a = t / freq;
        tpeS[2 * tid] = sinf(a);
        tpeS[2 * tid + 1] = cosf(a);
    }
    __syncthreads();

    // ---- build A (raw), two 16-row chunks; pack fp16 frags into Apk --------
#pragma unroll 1
    for (int half = 0; half < 2; half++) {
        const int base = g0 + half * 16;
        if (base + 16 <= n) {
            const float4* sem4 = (const float4*)p.sem;
            const float4* shs4 = (const float4*)p.shs;
#pragma unroll 1
            for (int i = tid; i < 512; i += 128) {       // sem: 16 x 128
                int r = i & 15, c = i >> 4;
                float4 v = sem4[(base + r) * 32 + c];
                float* d = H1raw + r * 257 + 59 + c * 4;
                d[0] = v.x; d[1] = v.y; d[2] = v.z; d[3] = v.w;
            }
#pragma unroll 1
            for (int i = tid; i < 192; i += 128) {       // shs: 16 x 48
                int r = i & 15, c = i >> 4;
                float4 v = shs4[(base + r) * 12 + c];
                float* d = H1raw + r * 257 + 11 + c * 4;
                d[0] = v.x; d[1] = v.y; d[2] = v.z; d[3] = v.w;
            }
#pragma unroll 1
            for (int i = tid; i < 208; i += 128) {       // pnt/rot/scl/dx
                int r = i & 15, j = i >> 4;
                int g = base + r;
                if (j < 3)       H1raw[r * 257 + j] = p.pnt[g * 3 + j];
                else if (j < 7)  H1raw[r * 257 + j] = p.rot[g * 4 + j - 3];
                else if (j < 10) H1raw[r * 257 + j] = p.scl[g * 3 + j - 7];
                else             H1raw[r * 257 + 177 + j] = p.dx[g * 3 + j - 10];
            }
            if (tid < 16) {
                int g = base + tid;
                H1raw[tid * 257 + 10]  = p.opa[g];
                H1raw[tid * 257 + 190] = p.tim[g];
                H1raw[tid * 257 + 255] = 0.0f;
            }
#pragma unroll 1
            for (int i = tid; i < 1024; i += 128) {      // tpe: 16 x 64
                int r = i & 15, j = i >> 4;
                H1raw[r * 257 + 191 + j] = tpeS[j];
            }
        } else {
            for (int idx = tid; idx < 16 * 256; idx += 128) {
                int lr = idx >> 8, k = idx & 255;
                int g = base + lr;
                float v = 0.0f;
                if (g < n && k < 255) {
                    if      (k < 3)    v = p.pnt[g * 3 + k];
                    else if (k < 7)    v = p.rot[g * 4 + (k - 3)];
                    else if (k < 10)   v = p.scl[g * 3 + (k - 7)];
                    else if (k == 10)  v = p.opa[g];
                    else if (k < 59)   v = p.shs[g * 48 + (k - 11)];
                    else if (k < 187)  v = p.sem[g * 128 + (k - 59)];
                    else if (k < 190)  v = p.dx[g * 3 + (k - 187)];
                    else if (k == 190) v = p.tim[g];
                    else               v = tpeS[k - 191];
                }
                H1raw[lr * 257 + k] = v;
            }
            if (tid < 16) H1raw[tid * 257 + 255] = 0.0f;
        }
        __syncthreads();
#pragma unroll 1
        for (int j = 0; j < 4; j++) {
            int ks = w * 4 + j;
            int r0 = gq, r1 = gq + 8;
            int k0 = ks * 16 + cc * 2;
            uint4 fr;
            fr.x = f2h2(fmaxf(H1raw[r0 * 257 + k0],     0.0f),
                        fmaxf(H1raw[r0 * 257 + k0 + 1], 0.0f));
            fr.y = f2h2(fmaxf(H1raw[r1 * 257 + k0],     0.0f),
                        fmaxf(H1raw[r1 * 257 + k0 + 1], 0.0f));
            fr.z = f2h2(fmaxf(H1raw[r0 * 257 + k0 + 8], 0.0f),
                        fmaxf(H1raw[r0 * 257 + k0 + 9], 0.0f));
            fr.w = f2h2(fmaxf(H1raw[r1 * 257 + k0 + 8], 0.0f),
                        fmaxf(H1raw[r1 * 257 + k0 + 9], 0.0f));
            *(uint4*)(sm + OFF_APK + apk1(ks, half, lane)) = fr;
        }
        __syncthreads();
    }
    if (tid < 32) { int g = g0 + tid; if (g < n) p.out[10 * n + g] = p.opa[g]; }

#pragma unroll 1
    for (int h = 0; h < 5; h++) {
        float acc[2][8][4];
#pragma unroll
        for (int a = 0; a < 2; a++)
#pragma unroll
            for (int b = 0; b < 8; b++)
#pragma unroll
                for (int e = 0; e < 4; e++) acc[a][b][e] = 0.0f;

        // ---------- GEMM1 mainloop: unrolled x2 ping-pong, no syncs ----------
        const unsigned char* hbase = g_w1pk + (size_t)(h * 16) * 8192;
#pragma unroll 1
        for (int ks = 0; ks < 16; ks += 2) {
            uint4 nb[4];
            {
                const uint4* b = (const uint4*)(hbase + (size_t)(ks + 1) * 8192);
#pragma unroll
                for (int i = 0; i < 4; i++) nb[i] = b[i * 128 + tid];
            }
            MMA_BLOCK(cb, ks);
            if (ks < 14) {
                const uint4* b = (const uint4*)(hbase + (size_t)(ks + 2) * 8192);
#pragma unroll
                for (int i = 0; i < 4; i++) cb[i] = b[i * 128 + tid];
            } else if (h < 4) {
                const uint4* b = (const uint4*)(g_w1pk + (size_t)((h + 1) * 16) * 8192);
#pragma unroll
                for (int i = 0; i < 4; i++) cb[i] = b[i * 128 + tid];
            }
            MMA_BLOCK(nb, ks + 1);
        }

        // b1 for this warp's n-slice
        float b1r[16];
#pragma unroll
        for (int nt = 0; nt < 8; nt++)
#pragma unroll
            for (int e = 0; e < 2; e++) {
                int nn = w * 64 + nt * 8 + cc * 2 + e;
                b1r[nt * 2 + e] = (nn < 255) ? p.b1[h][nn] : 0.0f;
            }

        if (h < 4) {
            // ---------- GEMM2 partials IN-REGISTER (C-frag == A-frag) --------
            // warp w covers k-windows 4w..4w+3; od<=8 fits one n-tile.
            float d[2][4] = {{0, 0, 0, 0}, {0, 0, 0, 0}};
            const uint2* wb = (const uint2*)g_w2pk + h * 16 * 32;
#pragma unroll
            for (int j = 0; j < 4; j++) {
                uint2 B = wb[(4 * w + j) * 32 + lane];
#pragma unroll
                for (int mt = 0; mt < 2; mt++) {
                    uint32_t A[4];
                    A[0] = f2h2(fmaxf(acc[mt][2 * j][0] + b1r[4 * j + 0], 0.0f),
                                fmaxf(acc[mt][2 * j][1] + b1r[4 * j + 1], 0.0f));
                    A[1] = f2h2(fmaxf(acc[mt][2 * j][2] + b1r[4 * j + 0], 0.0f),
                                fmaxf(acc[mt][2 * j][3] + b1r[4 * j + 1], 0.0f));
                    A[2] = f2h2(fmaxf(acc[mt][2 * j + 1][0] + b1r[4 * j + 2], 0.0f),
                                fmaxf(acc[mt][2 * j + 1][1] + b1r[4 * j + 3], 0.0f));
                    A[3] = f2h2(fmaxf(acc[mt][2 * j + 1][2] + b1r[4 * j + 2], 0.0f),
                                fmaxf(acc[mt][2 * j + 1][3] + b1r[4 * j + 3], 0.0f));
                    mma_f16(d[mt], A, B.x, B.y);
                }
            }
            // dump D-partials to red[h] (syncless; fenced by head-4 syncs)
            float4* redh = (float4*)(sm + OFF_SCR + h * 4096);
#pragma unroll
            for (int mt = 0; mt < 2; mt++)
                redh[w * 64 + mt * 32 + lane] =
                    make_float4(d[mt][0], d[mt][1], d[mt][2], d[mt][3]);
        } else {
            // ---------- head 4: pack H1 fp16 frags into Apk (A frags dead) ---
            __syncthreads();   // all warps done reading A frags; red writes done
#pragma unroll
            for (int j = 0; j < 4; j++) {
                const int ks2 = 4 * w + j;
#pragma unroll
                for (int mt = 0; mt < 2; mt++) {
                    uint4 fr;
                    fr.x = f2h2(fmaxf(acc[mt][2 * j][0] + b1r[4 * j + 0], 0.0f),
                                fmaxf(acc[mt][2 * j][1] + b1r[4 * j + 1], 0.0f));
                    fr.y = f2h2(fmaxf(acc[mt][2 * j][2] + b1r[4 * j + 0], 0.0f),
                                fmaxf(acc[mt][2 * j][3] + b1r[4 * j + 1], 0.0f));
                    fr.z = f2h2(fmaxf(acc[mt][2 * j + 1][0] + b1r[4 * j + 2], 0.0f),
                                fmaxf(acc[mt][2 * j + 1][1] + b1r[4 * j + 3], 0.0f));
                    fr.w = f2h2(fmaxf(acc[mt][2 * j + 1][2] + b1r[4 * j + 2], 0.0f),
                                fmaxf(acc[mt][2 * j + 1][3] + b1r[4 * j + 3], 0.0f));
                    *(uint4*)(sm + OFF_APK + apk1(ks2, mt, lane)) = fr;
                }
            }
            __syncthreads();   // H1pk + all red[h] visible

            // ---------- combined: reduce heads 0-3 (warp = head) + mask ------
            {
                const int hh = w;
                const float4* redb = (const float4*)(sm + OFF_SCR);
                float ds[2][4];
#pragma unroll
                for (int mt = 0; mt < 2; mt++) {
                    float4 a4 = make_float4(0.f, 0.f, 0.f, 0.f);
#pragma unroll
                    for (int wi = 0; wi < 4; wi++) {
                        float4 r = redb[hh * 256 + wi * 64 + mt * 32 + lane];
                        a4.x += r.x; a4.y += r.y; a4.z += r.z; a4.w += r.w;
                    }
                    ds[mt][0] = a4.x; ds[mt][1] = a4.y;
                    ds[mt][2] = a4.z; ds[mt][3] = a4.w;
                }
                if (hh == 0 && cc == 0) {
                    float b20 = p.b2[0][0];
#pragma unroll
                    for (int mt = 0; mt < 2; mt++) {
                        maskS[mt * 16 + gq]     = 1.0f / (1.0f + expf(-(ds[mt][0] + b20)));
                        maskS[mt * 16 + gq + 8] = 1.0f / (1.0f + expf(-(ds[mt][2] + b20)));
                    }
                }
                __syncthreads();    // maskS visible
                if (hh >= 1) {
                    const int od = (hh == 3) ? 4 : 3;
#pragma unroll
                    for (int mt = 0; mt < 2; mt++)
#pragma unroll
                        for (int e = 0; e < 4; e++) {
                            int o = cc * 2 + (e & 1);
                            if (o < od) {
                                int m = mt * 16 + gq + ((e >> 1) << 3);
                                int g = g0 + m;
                                if (g < n) {
                                    float val = ds[mt][e] + p.b2[hh][o];
                                    float mk = maskS[m];
                                    if (hh == 1) {
                                        p.out[59 * n + g * 3 + o] = val;
                                        p.out[g * 3 + o] = p.pnt[g * 3 + o] + val * mk;
                                    } else if (hh == 2) {
                                        p.out[3 * n + g * 3 + o] = p.scl[g * 3 + o] + val * mk;
                                    } else {
                                        p.out[6 * n + g * 4 + o] = p.rot[g * 4 + o] + val * mk;
                                    }
                                }
                            }
                        }
                }
            }

            // ---------- head 4 GEMM2 on HMMA: 12 jobs over 4 warps ----------
#pragma unroll 1
            for (int jb = 0; jb < 3; jb++) {
                int t = w + 4 * jb;            // 0..11
                int mt = t / 6, nt2 = t % 6;
                float d0[4] = {0, 0, 0, 0};
                const uint2* wb = (const uint2*)g_w2pk + (4 + nt2) * 16 * 32;
                uint2 B = wb[lane];
#pragma unroll 1
                for (int ks2 = 0; ks2 < 16; ks2++) {
                    uint2 Bn;
                    if (ks2 < 15) Bn = wb[(ks2 + 1) * 32 + lane];
                    uint4 ah4 = *(const uint4*)(sm + OFF_APK + apk1(ks2, mt, lane));
                    uint32_t ah[4] = {ah4.x, ah4.y, ah4.z, ah4.w};
                    mma_f16(d0, ah, B.x, B.y);
                    if (ks2 < 15) B = Bn;
                }
#pragma unroll
                for (int e = 0; e < 4; e++) {
                    int o = nt2 * 8 + cc * 2 + (e & 1);
                    int m = mt * 16 + gq + ((e >> 1) << 3);
                    int g = g0 + m;
                    if (g < n) {
                        float val = d0[e] + p.b2[4][o];
                        float mk = maskS[m];
                        p.out[oDSH + g * 48 + o] = val;
                        p.out[oSHS + g * 48 + o] = p.shs[g * 48 + o] + val * mk;
                    }
                }
            }
        }
    }
}

extern "C" void kernel_launch(void* const* d_in, const int* in_sizes, int n_in,
                              void* d_out, int out_size) {
    Params p;
    p.opa = (const float*)d_in[0];
    p.shs = (const float*)d_in[1];
    p.tim = (const float*)d_in[2];
    p.sem = (const float*)d_in[3];
    p.pnt = (const float*)d_in[4];
    p.scl = (const float*)d_in[5];
    p.rot = (const float*)d_in[6];
    p.dx  = (const float*)d_in[7];
    for (int h = 0; h < 5; h++) {
        p.w1[h] = (const float*)d_in[8 + h * 4 + 0];
        p.b1[h] = (const float*)d_in[8 + h * 4 + 1];
        p.w2[h] = (const float*)d_in[8 + h * 4 + 2];
        p.b2[h] = (const float*)d_in[8 + h * 4 + 3];
    }
    p.out = (float*)d_out;
    p.n   = in_sizes[0];

    prep_all<<<60, 256>>>(p.w1[0], p.w1[1], p.w1[2], p.w1[3], p.w1[4],
                          p.w2[0], p.w2[1], p.w2[2], p.w2[3], p.w2[4]);

    cudaFuncSetAttribute(deform11, cudaFuncAttributeMaxDynamicSharedMemorySize, SMEM_BYTES);
    const int grid = (p.n + 31) / 32;   // 6250
    deform11<<<grid, 128, SMEM_BYTES>>>(p);
}

// round 16
// speedup vs baseline: 2.1155x; 1.1038x over previous
#include <cuda_runtime.h>
#include <cuda_fp16.h>
#include <cstdint>

// ============================================================================
// Deformation net, HMMA fp16 single-pass (fp32 accum).
// CTA = 32 points, 128 threads (4 warps), 4 CTAs/SM.
// KEY: tpe columns (191..254) are constant across points -> folded into a
// precomputed bias bc = b1 + relu(tpe)@W1[191:255] by the prep kernel.
// GEMM1 K = 192 (12 k-steps) instead of 256: -25% tensor work & traffic.
//  - GEMM1: ks-loop unrolled x2 ping-pong, B via LDG.128, no syncs.
//  - Heads 0-3 GEMM2: in-register HMMA partials (C-frag == A-frag layout),
//    syncless D-partial dump to red[h]; one combined reduce/output phase.
//  - Head 4 GEMM2: H1 (K=256) packed into dead A-frag region, 12 HMMA jobs.
//  - Epilogue inputs (pnt/rot/scl/shs) persisted in smem rawS (no tail LDGs).
// ============================================================================

#define DEVI __device__ __forceinline__

// W1 packed frags: [head][ks 0..11][slot 0..3][tid 0..127] x uint4 = 480KB
__device__ __align__(16) unsigned char g_w1pk[5 * 12 * 4 * 128 * 16];
// W2 packed frags: slots 0..3 = heads 0..3 (nt2=0); 4..9 = head4 nt2 0..5
__device__ __align__(8) unsigned char g_w2pk[10 * 16 * 32 * 8];
// combined bias: bc[h][n] = b1[h][n] + sum_j relu(tpe_j) * W1[h][191+j][n]
__device__ float g_bc[5][256];

DEVI uint32_t f2h2(float x, float y) {
    __half2 h = __floats2half2_rn(x, y);
    return *(uint32_t*)&h;
}

__global__ void prep_all(const float* w10, const float* w11, const float* w12,
                         const float* w13, const float* w14,
                         const float* w20, const float* w21, const float* w22,
                         const float* w23, const float* w24,
                         const float* b10, const float* b11, const float* b12,
                         const float* b13, const float* b14,
                         const float* tim) {
    int idx = blockIdx.x * blockDim.x + threadIdx.x;
    if (idx < 7680) {                  // 5 heads * 12 ks * 128 tid
        const float* ws[5] = {w10, w11, w12, w13, w14};
        int h = idx / 1536, ks = (idx >> 7) % 12, tid = idx & 127;
        int w = tid >> 5, lane = tid & 31;
        int gq = lane >> 2, cc = lane & 3;
        const float* W = ws[h];
        uint4* base = (uint4*)(g_w1pk + (size_t)(h * 12 + ks) * 8192);
#pragma unroll
        for (int s = 0; s < 4; s++) {
            uint32_t fr[4];
#pragma unroll
            for (int half = 0; half < 2; half++) {
                int ntl = 2 * s + half;
                int nn = w * 64 + ntl * 8 + gq;
                int k0 = ks * 16 + cc * 2;
                float v[4];
                int kk[4] = {k0, k0 + 1, k0 + 8, k0 + 9};
#pragma unroll
                for (int j = 0; j < 4; j++)
                    v[j] = (kk[j] < 191 && nn < 255) ? W[kk[j] * 255 + nn] : 0.0f;
                fr[half * 2 + 0] = f2h2(v[0], v[1]);
                fr[half * 2 + 1] = f2h2(v[2], v[3]);
            }
            base[s * 128 + tid] = make_uint4(fr[0], fr[1], fr[2], fr[3]);
        }
    } else if (idx < 7680 + 5120) {
        const float* ws[5] = {w20, w21, w22, w23, w24};
        const int ods[5] = {1, 3, 3, 4, 48};
        int j = idx - 7680;
        int slot = j >> 9, ks2 = (j >> 5) & 15, lane = j & 31;
        int head = (slot < 4) ? slot : 4;
        int nt2  = (slot < 4) ? 0 : slot - 4;
        int od = ods[head];
        const float* W = ws[head];
        int nn = nt2 * 8 + (lane >> 2);
        int k0 = ks2 * 16 + (lane & 3) * 2;
        float v[4];
        int kk[4] = {k0, k0 + 1, k0 + 8, k0 + 9};
#pragma unroll
        for (int q = 0; q < 4; q++)
            v[q] = (kk[q] < 255 && nn < od) ? W[kk[q] * od + nn] : 0.0f;
        ((uint2*)g_w2pk)[(slot * 16 + ks2) * 32 + lane] =
            make_uint2(f2h2(v[0], v[1]), f2h2(v[2], v[3]));
    } else if (idx < 7680 + 5120 + 1280) {
        // bc[h][n] = b1[h][n] + sum_j relu(tpe_j) * W1[h][191+j][n]
        const float* ws[5] = {w10, w11, w12, w13, w14};
        const float* bs[5] = {b10, b11, b12, b13, b14};
        int j = idx - (7680 + 5120);
        int h = j >> 8, nn = j & 255;
        if (nn < 255) {
            float t = tim[0];
            float s = 0.0f;
#pragma unroll 1
            for (int q = 0; q < 64; q++) {
                int m = q >> 1;
                float freq = exp2f((float)(2 * m) * (13.287712379549449f / 32.0f));
                float a = t / freq;
                float v = (q & 1) ? cosf(a) : sinf(a);
                v = fmaxf(v, 0.0f);
                s += v * ws[h][(191 + q) * 255 + nn];
            }
            g_bc[h][nn] = bs[h][nn] + s;
        } else {
            g_bc[h][nn] = 0.0f;
        }
    }
}

DEVI void mma_f16(float* d, const uint32_t* a, uint32_t b0, uint32_t b1) {
    asm("mma.sync.aligned.m16n8k16.row.col.f32.f16.f16.f32 "
        "{%0,%1,%2,%3}, {%4,%5,%6,%7}, {%8,%9}, {%0,%1,%2,%3};"
        : "+f"(d[0]), "+f"(d[1]), "+f"(d[2]), "+f"(d[3])
        : "r"(a[0]), "r"(a[1]), "r"(a[2]), "r"(a[3]), "r"(b0), "r"(b1));
}

struct Params {
    const float* opa; const float* shs; const float* tim; const float* sem;
    const float* pnt; const float* scl; const float* rot; const float* dx;
    const float* w1[5]; const float* b1[5]; const float* w2[5]; const float* b2[5];
    float* out; int n;
};

// ---- smem layout (bytes), ~40.7 KB (4 CTAs/SM) --------------------------------
// APK : A frags (12 ks used by GEMM1) / H1pk frags (16 ks, head4)   16384
// SCR : staging 16x257 f32 (16448); later red[4] x 4KB D-partials
// RAWS: persisted inputs [32 rows][60 f32]: pnt0-2 rot3-6 scl7-9 shs10-57
#define OFF_APK   0
#define OFF_SCR   16384
#define OFF_RAWS  (OFF_SCR + 16448)
#define OFF_MASK  (OFF_RAWS + 7680)
#define SMEM_BYTES (OFF_MASK + 128)

DEVI uint32_t apk1(int ks, int mt, int lane) {
    return (uint32_t)(((ks * 2 + mt) * 32 + lane) * 16);
}

#define MMA_BLOCK(BUF, KS)                                                     \
    do {                                                                       \
        const uint32_t bf[8][2] = {                                            \
            {BUF[0].x, BUF[0].y}, {BUF[0].z, BUF[0].w},                        \
            {BUF[1].x, BUF[1].y}, {BUF[1].z, BUF[1].w},                        \
            {BUF[2].x, BUF[2].y}, {BUF[2].z, BUF[2].w},                        \
            {BUF[3].x, BUF[3].y}, {BUF[3].z, BUF[3].w}};                       \
        _Pragma("unroll")                                                      \
        for (int mt = 0; mt < 2; mt++) {                                       \
            uint4 q = *(const uint4*)(sm + OFF_APK + apk1((KS), mt, lane));    \
            uint32_t A[4] = {q.x, q.y, q.z, q.w};                              \
            _Pragma("unroll")                                                  \
            for (int nt = 0; nt < 8; nt++)                                     \
                mma_f16(acc[mt][nt], A, bf[nt][0], bf[nt][1]);                 \
        }                                                                      \
    } while (0)

__global__ __launch_bounds__(128, 4)
void deform12(Params p) {
    extern __shared__ __align__(16) unsigned char sm[];
    float*  H1raw = (float*)(sm + OFF_SCR);     // 16 rows x stride 257
    float*  rawS  = (float*)(sm + OFF_RAWS);    // 32 rows x 60
    float*  maskS = (float*)(sm + OFF_MASK);

    const int tid = threadIdx.x, w = tid >> 5, lane = tid & 31;
    const int gq = lane >> 2, cc = lane & 3;
    const int n = p.n, g0 = blockIdx.x * 32;
    const int oSHS = 11 * n, oDSH = 62 * n;

    // prefetch B(h=0, ks=0)
    uint4 cb[4];
    {
        const uint4* b = (const uint4*)g_w1pk;
#pragma unroll
        for (int i = 0; i < 4; i++) cb[i] = b[i * 128 + tid];
    }

    // ---- build A (raw), two 16-row chunks; pack fp16 frags (12 ks) ---------
#pragma unroll 1
    for (int half = 0; half < 2; half++) {
        const int base = g0 + half * 16;
        float* rawH = rawS + half * 16 * 60;
        if (base + 16 <= n) {
            const float4* sem4 = (const float4*)p.sem;
            const float4* shs4 = (const float4*)p.shs;
#pragma unroll 1
            for (int i = tid; i < 512; i += 128) {       // sem: 16 x 128
                int r = i & 15, c = i >> 4;
                float4 v = sem4[(base + r) * 32 + c];
                float* d = H1raw + r * 257 + 59 + c * 4;
                d[0] = v.x; d[1] = v.y; d[2] = v.z; d[3] = v.w;
            }
#pragma unroll 1
            for (int i = tid; i < 192; i += 128) {       // shs: 16 x 48 (+rawS)
                int r = i & 15, c = i >> 4;
                float4 v = shs4[(base + r) * 12 + c];
                float* d = H1raw + r * 257 + 11 + c * 4;
                d[0] = v.x; d[1] = v.y; d[2] = v.z; d[3] = v.w;
                float* rw = rawH + r * 60 + 10 + c * 4;
                rw[0] = v.x; rw[1] = v.y; rw[2] = v.z; rw[3] = v.w;
            }
#pragma unroll 1
            for (int i = tid; i < 208; i += 128) {       // pnt/rot/scl/dx
                int r = i & 15, j = i >> 4;
                int g = base + r;
                float v;
                if (j < 3)       v = p.pnt[g * 3 + j];
                else if (j < 7)  v = p.rot[g * 4 + j - 3];
                else if (j < 10) v = p.scl[g * 3 + j - 7];
                else             v = p.dx[g * 3 + j - 10];
                if (j < 10) {
                    H1raw[r * 257 + j] = v;
                    rawH[r * 60 + j] = v;
                } else {
                    H1raw[r * 257 + 177 + j] = v;        // cols 187..189
                }
            }
            if (tid < 16) {
                int g = base + tid;
                H1raw[tid * 257 + 10]  = p.opa[g];
                H1raw[tid * 257 + 190] = p.tim[g];
                H1raw[tid * 257 + 191] = 0.0f;           // pad col (ks=11 tail)
            }
        } else {
            for (int idx = tid; idx < 16 * 192; idx += 128) {
                int lr = idx / 192, k = idx % 192;
                int g = base + lr;
                float v = 0.0f;
                if (g < n && k < 191) {
                    if      (k < 3)    v = p.pnt[g * 3 + k];
                    else if (k < 7)    v = p.rot[g * 4 + (k - 3)];
                    else if (k < 10)   v = p.scl[g * 3 + (k - 7)];
                    else if (k == 10)  v = p.opa[g];
                    else if (k < 59)   v = p.shs[g * 48 + (k - 11)];
                    else if (k < 187)  v = p.sem[g * 128 + (k - 59)];
                    else if (k < 190)  v = p.dx[g * 3 + (k - 187)];
                    else               v = p.tim[g];
                }
                H1raw[lr * 257 + k] = v;
                if (k < 10) rawH[lr * 60 + k] = v;
                else if (k >= 11 && k < 59) rawH[lr * 60 + k - 1] = v;
            }
        }
        __syncthreads();
        // pack 12 ks x 2 halves: warp packs ks = w*3 + j (j 0..2); relu here
#pragma unroll 1
        for (int j = 0; j < 3; j++) {
            int ks = w * 3 + j;
            int r0 = gq, r1 = gq + 8;
            int k0 = ks * 16 + cc * 2;
            uint4 fr;
            fr.x = f2h2(fmaxf(H1raw[r0 * 257 + k0],     0.0f),
                        fmaxf(H1raw[r0 * 257 + k0 + 1], 0.0f));
            fr.y = f2h2(fmaxf(H1raw[r1 * 257 + k0],     0.0f),
                        fmaxf(H1raw[r1 * 257 + k0 + 1], 0.0f));
            fr.z = f2h2(fmaxf(H1raw[r0 * 257 + k0 + 8], 0.0f),
                        fmaxf(H1raw[r0 * 257 + k0 + 9], 0.0f));
            fr.w = f2h2(fmaxf(H1raw[r1 * 257 + k0 + 8], 0.0f),
                        fmaxf(H1raw[r1 * 257 + k0 + 9], 0.0f));
            *(uint4*)(sm + OFF_APK + apk1(ks, half, lane)) = fr;
        }
        __syncthreads();
    }
    if (tid < 32) { int g = g0 + tid; if (g < n) p.out[10 * n + g] = p.opa[g]; }

#pragma unroll 1
    for (int h = 0; h < 5; h++) {
        float acc[2][8][4];
#pragma unroll
        for (int a = 0; a < 2; a++)
#pragma unroll
            for (int b = 0; b < 8; b++)
#pragma unroll
                for (int e = 0; e < 4; e++) acc[a][b][e] = 0.0f;

        // ---------- GEMM1 mainloop: K=192 (12 ks), unrolled x2 ping-pong -----
        const unsigned char* hbase = g_w1pk + (size_t)(h * 12) * 8192;
#pragma unroll 1
        for (int ks = 0; ks < 12; ks += 2) {
            uint4 nb[4];
            {
                const uint4* b = (const uint4*)(hbase + (size_t)(ks + 1) * 8192);
#pragma unroll
                for (int i = 0; i < 4; i++) nb[i] = b[i * 128 + tid];
            }
            MMA_BLOCK(cb, ks);
            if (ks < 10) {
                const uint4* b = (const uint4*)(hbase + (size_t)(ks + 2) * 8192);
#pragma unroll
                for (int i = 0; i < 4; i++) cb[i] = b[i * 128 + tid];
            } else if (h < 4) {
                const uint4* b = (const uint4*)(g_w1pk + (size_t)((h + 1) * 12) * 8192);
#pragma unroll
                for (int i = 0; i < 4; i++) cb[i] = b[i * 128 + tid];
            }
            MMA_BLOCK(nb, ks + 1);
        }

        // combined bias bc = b1 + cvec(tpe), for this warp's n-slice
        float b1r[16];
#pragma unroll
        for (int nt = 0; nt < 8; nt++)
#pragma unroll
            for (int e = 0; e < 2; e++) {
                int nn = w * 64 + nt * 8 + cc * 2 + e;
                b1r[nt * 2 + e] = g_bc[h][nn];
            }

        if (h < 4) {
            // ---------- GEMM2 partials IN-REGISTER (C-frag == A-frag) --------
            float d[2][4] = {{0, 0, 0, 0}, {0, 0, 0, 0}};
            const uint2* wb = (const uint2*)g_w2pk + h * 16 * 32;
#pragma unroll
            for (int j = 0; j < 4; j++) {
                uint2 B = wb[(4 * w + j) * 32 + lane];
#pragma unroll
                for (int mt = 0; mt < 2; mt++) {
                    uint32_t A[4];
                    A[0] = f2h2(fmaxf(acc[mt][2 * j][0] + b1r[4 * j + 0], 0.0f),
                                fmaxf(acc[mt][2 * j][1] + b1r[4 * j + 1], 0.0f));
                    A[1] = f2h2(fmaxf(acc[mt][2 * j][2] + b1r[4 * j + 0], 0.0f),
                                fmaxf(acc[mt][2 * j][3] + b1r[4 * j + 1], 0.0f));
                    A[2] = f2h2(fmaxf(acc[mt][2 * j + 1][0] + b1r[4 * j + 2], 0.0f),
                                fmaxf(acc[mt][2 * j + 1][1] + b1r[4 * j + 3], 0.0f));
                    A[3] = f2h2(fmaxf(acc[mt][2 * j + 1][2] + b1r[4 * j + 2], 0.0f),
                                fmaxf(acc[mt][2 * j + 1][3] + b1r[4 * j + 3], 0.0f));
                    mma_f16(d[mt], A, B.x, B.y);
                }
            }
            float4* redh = (float4*)(sm + OFF_SCR + h * 4096);
#pragma unroll
            for (int mt = 0; mt < 2; mt++)
                redh[w * 64 + mt * 32 + lane] =
                    make_float4(d[mt][0], d[mt][1], d[mt][2], d[mt][3]);
        } else {
            // ---------- head 4: pack H1 fp16 frags (K=256, 16 ks) into APK ---
            __syncthreads();   // all warps done reading A frags; red writes done
#pragma unroll
            for (int j = 0; j < 4; j++) {
                const int ks2 = 4 * w + j;
#pragma unroll
                for (int mt = 0; mt < 2; mt++) {
                    uint4 fr;
                    fr.x = f2h2(fmaxf(acc[mt][2 * j][0] + b1r[4 * j + 0], 0.0f),
                                fmaxf(acc[mt][2 * j][1] + b1r[4 * j + 1], 0.0f));
                    fr.y = f2h2(fmaxf(acc[mt][2 * j][2] + b1r[4 * j + 0], 0.0f),
                                fmaxf(acc[mt][2 * j][3] + b1r[4 * j + 1], 0.0f));
                    fr.z = f2h2(fmaxf(acc[mt][2 * j + 1][0] + b1r[4 * j + 2], 0.0f),
                                fmaxf(acc[mt][2 * j + 1][1] + b1r[4 * j + 3], 0.0f));
                    fr.w = f2h2(fmaxf(acc[mt][2 * j + 1][2] + b1r[4 * j + 2], 0.0f),
                                fmaxf(acc[mt][2 * j + 1][3] + b1r[4 * j + 3], 0.0f));
                    *(uint4*)(sm + OFF_APK + apk1(ks2, mt, lane)) = fr;
                }
            }
            __syncthreads();   // H1pk + all red[h] visible

            // ---------- combined: reduce heads 0-3 (warp = head) + mask ------
            {
                const int hh = w;
                const float4* redb = (const float4*)(sm + OFF_SCR);
                float ds[2][4];
#pragma unroll
                for (int mt = 0; mt < 2; mt++) {
                    float4 a4 = make_float4(0.f, 0.f, 0.f, 0.f);
#pragma unroll
                    for (int wi = 0; wi < 4; wi++) {
                        float4 r = redb[hh * 256 + wi * 64 + mt * 32 + lane];
                        a4.x += r.x; a4.y += r.y; a4.z += r.z; a4.w += r.w;
                    }
                    ds[mt][0] = a4.x; ds[mt][1] = a4.y;
                    ds[mt][2] = a4.z; ds[mt][3] = a4.w;
                }
                if (hh == 0 && cc == 0) {
                    float b20 = p.b2[0][0];
#pragma unroll
                    for (int mt = 0; mt < 2; mt++) {
                        maskS[mt * 16 + gq]     = 1.0f / (1.0f + expf(-(ds[mt][0] + b20)));
                        maskS[mt * 16 + gq + 8] = 1.0f / (1.0f + expf(-(ds[mt][2] + b20)));
                    }
                }
                __syncthreads();    // maskS visible
                if (hh >= 1) {
                    const int od = (hh == 3) ? 4 : 3;
#pragma unroll
                    for (int mt = 0; mt < 2; mt++)
#pragma unroll
                        for (int e = 0; e < 4; e++) {
                            int o = cc * 2 + (e & 1);
                            if (o < od) {
                                int m = mt * 16 + gq + ((e >> 1) << 3);
                                int g = g0 + m;
                                if (g < n) {
                                    float val = ds[mt][e] + p.b2[hh][o];
                                    float mk = maskS[m];
                                    if (hh == 1) {
                                        p.out[59 * n + g * 3 + o] = val;
                                        p.out[g * 3 + o] = rawS[m * 60 + o] + val * mk;
                                    } else if (hh == 2) {
                                        p.out[3 * n + g * 3 + o] =
                                            rawS[m * 60 + 7 + o] + val * mk;
                                    } else {
                                        p.out[6 * n + g * 4 + o] =
                                            rawS[m * 60 + 3 + o] + val * mk;
                                    }
                                }
                            }
                        }
                }
            }

            // ---------- head 4 GEMM2 on HMMA: 12 jobs over 4 warps ----------
#pragma unroll 1
            for (int jb = 0; jb < 3; jb++) {
                int t = w + 4 * jb;            // 0..11
                int mt = t / 6, nt2 = t % 6;
                float d0[4] = {0, 0, 0, 0};
                const uint2* wb = (const uint2*)g_w2pk + (4 + nt2) * 16 * 32;
                uint2 B = wb[lane];
#pragma unroll 1
                for (int ks2 = 0; ks2 < 16; ks2++) {
                    uint2 Bn;
                    if (ks2 < 15) Bn = wb[(ks2 + 1) * 32 + lane];
                    uint4 ah4 = *(const uint4*)(sm + OFF_APK + apk1(ks2, mt, lane));
                    uint32_t ah[4] = {ah4.x, ah4.y, ah4.z, ah4.w};
                    mma_f16(d0, ah, B.x, B.y);
                    if (ks2 < 15) B = Bn;
                }
#pragma unroll
                for (int e = 0; e < 4; e++) {
                    int o = nt2 * 8 + cc * 2 + (e & 1);
                    int m = mt * 16 + gq + ((e >> 1) << 3);
                    int g = g0 + m;
                    if (g < n) {
                        float val = d0[e] + p.b2[4][o];
                        float mk = maskS[m];
                        p.out[oDSH + g * 48 + o] = val;
                        p.out[oSHS + g * 48 + o] = rawS[m * 60 + 10 + o] + val * mk;
                    }
                }
            }
        }
    }
}

extern "C" void kernel_launch(void* const* d_in, const int* in_sizes, int n_in,
                              void* d_out, int out_size) {
    Params p;
    p.opa = (const float*)d_in[0];
    p.shs = (const float*)d_in[1];
    p.tim = (const float*)d_in[2];
    p.sem = (const float*)d_in[3];
    p.pnt = (const float*)d_in[4];
    p.scl = (const float*)d_in[5];
    p.rot = (const float*)d_in[6];
    p.dx  = (const float*)d_in[7];
    for (int h = 0; h < 5; h++) {
        p.w1[h] = (const float*)d_in[8 + h * 4 + 0];
        p.b1[h] = (const float*)d_in[8 + h * 4 + 1];
        p.w2[h] = (const float*)d_in[8 + h * 4 + 2];
        p.b2[h] = (const float*)d_in[8 + h * 4 + 3];
    }
    p.out = (float*)d_out;
    p.n   = in_sizes[0];

    prep_all<<<55, 256>>>(p.w1[0], p.w1[1], p.w1[2], p.w1[3], p.w1[4],
                          p.w2[0], p.w2[1], p.w2[2], p.w2[3], p.w2[4],
                          p.b1[0], p.b1[1], p.b1[2], p.b1[3], p.b1[4],
                          p.tim);

    cudaFuncSetAttribute(deform12, cudaFuncAttributeMaxDynamicSharedMemorySize, SMEM_BYTES);
    const int grid = (p.n + 31) / 32;   // 6250
    deform12<<<grid, 128, SMEM_BYTES>>>(p);
}

// round 17
// speedup vs baseline: 2.2150x; 1.0470x over previous
#include <cuda_runtime.h>
#include <cuda_fp16.h>
#include <cstdint>

// ============================================================================
// Deformation net, HMMA fp16 single-pass (fp32 accum). PERSISTENT CTAs.
// Grid = 4*148; CTA loops over 32-point tiles (phase drift persists).
// 128 threads (4 warps), 4 CTAs/SM. tpe columns folded into bias (K=192).
//  - GEMM1: 12 ks, unrolled x2 ping-pong, B via LDG.128, no syncs.
//  - Heads 0-3 GEMM2: in-register HMMA partials, syncless dump to red[h];
//    one combined reduce/output phase. Head 4 GEMM2: H1pk + 12 HMMA jobs.
//  - Epilogue inputs persisted in smem rawS.
// ============================================================================

#define DEVI __device__ __forceinline__

// W1 packed frags: [head][ks 0..11][slot 0..3][tid 0..127] x uint4 = 480KB
__device__ __align__(16) unsigned char g_w1pk[5 * 12 * 4 * 128 * 16];
// W2 packed frags: slots 0..3 = heads 0..3 (nt2=0); 4..9 = head4 nt2 0..5
__device__ __align__(8) unsigned char g_w2pk[10 * 16 * 32 * 8];
// combined bias: bc[h][n] = b1[h][n] + sum_j relu(tpe_j) * W1[h][191+j][n]
__device__ float g_bc[5][256];

DEVI uint32_t f2h2(float x, float y) {
    __half2 h = __floats2half2_rn(x, y);
    return *(uint32_t*)&h;
}

// ---- prep: fully parallel (46080 threads) ------------------------------------
__global__ void prep_all(const float* w10, const float* w11, const float* w12,
                         const float* w13, const float* w14,
                         const float* w20, const float* w21, const float* w22,
                         const float* w23, const float* w24,
                         const float* b10, const float* b11, const float* b12,
                         const float* b13, const float* b14,
                         const float* tim) {
    int idx = blockIdx.x * blockDim.x + threadIdx.x;
    if (idx < 30720) {                 // W1 pack: one uint4 per thread
        const float* ws[5] = {w10, w11, w12, w13, w14};
        int h = idx / 6144, rem = idx % 6144;
        int ks = rem >> 9, s = (rem >> 7) & 3, tid = rem & 127;
        int w = tid >> 5, lane = tid & 31;
        int gq = lane >> 2, cc = lane & 3;
        const float* W = ws[h];
        uint32_t fr[4];
#pragma unroll
        for (int half = 0; half < 2; half++) {
            int ntl = 2 * s + half;
            int nn = w * 64 + ntl * 8 + gq;
            int k0 = ks * 16 + cc * 2;
            float v[4];
            int kk[4] = {k0, k0 + 1, k0 + 8, k0 + 9};
#pragma unroll
            for (int j = 0; j < 4; j++)
                v[j] = (kk[j] < 191 && nn < 255) ? W[kk[j] * 255 + nn] : 0.0f;
            fr[half * 2 + 0] = f2h2(v[0], v[1]);
            fr[half * 2 + 1] = f2h2(v[2], v[3]);
        }
        uint4* base = (uint4*)(g_w1pk + (size_t)(h * 12 + ks) * 8192);
        base[s * 128 + tid] = make_uint4(fr[0], fr[1], fr[2], fr[3]);
    } else if (idx < 30720 + 5120) {   // W2 pack
        const float* ws[5] = {w20, w21, w22, w23, w24};
        const int ods[5] = {1, 3, 3, 4, 48};
        int j = idx - 30720;
        int slot = j >> 9, ks2 = (j >> 5) & 15, lane = j & 31;
        int head = (slot < 4) ? slot : 4;
        int nt2  = (slot < 4) ? 0 : slot - 4;
        int od = ods[head];
        const float* W = ws[head];
        int nn = nt2 * 8 + (lane >> 2);
        int k0 = ks2 * 16 + (lane & 3) * 2;
        float v[4];
        int kk[4] = {k0, k0 + 1, k0 + 8, k0 + 9};
#pragma unroll
        for (int q = 0; q < 4; q++)
            v[q] = (kk[q] < 255 && nn < od) ? W[kk[q] * od + nn] : 0.0f;
        ((uint2*)g_w2pk)[(slot * 16 + ks2) * 32 + lane] =
            make_uint2(f2h2(v[0], v[1]), f2h2(v[2], v[3]));
    } else if (idx < 30720 + 5120 + 10240) {
        // bc: 8 threads per (h, nn), shfl-reduced (deterministic)
        const float* ws[5] = {w10, w11, w12, w13, w14};
        const float* bs[5] = {b10, b11, b12, b13, b14};
        int j = idx - (30720 + 5120);
        int lane8 = j & 7, group = j >> 3;
        int h = group >> 8, nn = group & 255;
        float t = tim[0];
        float s = 0.0f;
        if (nn < 255) {
#pragma unroll
            for (int i = 0; i < 8; i++) {
                int q = lane8 * 8 + i;
                int m = q >> 1;
                float freq = exp2f((float)(2 * m) * (13.287712379549449f / 32.0f));
                float a = t / freq;
                float v = (q & 1) ? cosf(a) : sinf(a);
                v = fmaxf(v, 0.0f);
                s += v * ws[h][(191 + q) * 255 + nn];
            }
        }
        s += __shfl_xor_sync(0xffffffffu, s, 1);
        s += __shfl_xor_sync(0xffffffffu, s, 2);
        s += __shfl_xor_sync(0xffffffffu, s, 4);
        if (lane8 == 0)
            g_bc[h][nn] = (nn < 255) ? (bs[h][nn] + s) : 0.0f;
    }
}

DEVI void mma_f16(float* d, const uint32_t* a, uint32_t b0, uint32_t b1) {
    asm("mma.sync.aligned.m16n8k16.row.col.f32.f16.f16.f32 "
        "{%0,%1,%2,%3}, {%4,%5,%6,%7}, {%8,%9}, {%0,%1,%2,%3};"
        : "+f"(d[0]), "+f"(d[1]), "+f"(d[2]), "+f"(d[3])
        : "r"(a[0]), "r"(a[1]), "r"(a[2]), "r"(a[3]), "r"(b0), "r"(b1));
}

struct Params {
    const float* opa; const float* shs; const float* tim; const float* sem;
    const float* pnt; const float* scl; const float* rot; const float* dx;
    const float* w1[5]; const float* b1[5]; const float* w2[5]; const float* b2[5];
    float* out; int n; int ntiles;
};

// ---- smem layout (bytes), ~40.7 KB (4 CTAs/SM) --------------------------------
#define OFF_APK   0
#define OFF_SCR   16384
#define OFF_RAWS  (OFF_SCR + 16448)
#define OFF_MASK  (OFF_RAWS + 7680)
#define SMEM_BYTES (OFF_MASK + 128)

DEVI uint32_t apk1(int ks, int mt, int lane) {
    return (uint32_t)(((ks * 2 + mt) * 32 + lane) * 16);
}

#define MMA_BLOCK(BUF, KS)                                                     \
    do {                                                                       \
        const uint32_t bf[8][2] = {                                            \
            {BUF[0].x, BUF[0].y}, {BUF[0].z, BUF[0].w},                        \
            {BUF[1].x, BUF[1].y}, {BUF[1].z, BUF[1].w},                        \
            {BUF[2].x, BUF[2].y}, {BUF[2].z, BUF[2].w},                        \
            {BUF[3].x, BUF[3].y}, {BUF[3].z, BUF[3].w}};                       \
        _Pragma("unroll")                                                      \
        for (int mt = 0; mt < 2; mt++) {                                       \
            uint4 q = *(const uint4*)(sm + OFF_APK + apk1((KS), mt, lane));    \
            uint32_t A[4] = {q.x, q.y, q.z, q.w};                              \
            _Pragma("unroll")                                                  \
            for (int nt = 0; nt < 8; nt++)                                     \
                mma_f16(acc[mt][nt], A, bf[nt][0], bf[nt][1]);                 \
        }                                                                      \
    } while (0)

__global__ __launch_bounds__(128, 4)
void deform13(Params p) {
    extern __shared__ __align__(16) unsigned char sm[];
    float*  H1raw = (float*)(sm + OFF_SCR);     // 16 rows x stride 257
    float*  rawS  = (float*)(sm + OFF_RAWS);    // 32 rows x 60
    float*  maskS = (float*)(sm + OFF_MASK);

    const int tid = threadIdx.x, w = tid >> 5, lane = tid & 31;
    const int gq = lane >> 2, cc = lane & 3;
    const int n = p.n;
    const int oSHS = 11 * n, oDSH = 62 * n;

#pragma unroll 1
    for (int tile = blockIdx.x; tile < p.ntiles; tile += gridDim.x) {
        const int g0 = tile * 32;
        __syncthreads();   // fence rawS/maskS/H1raw reuse across tiles

        // prefetch B(h=0, ks=0)
        uint4 cb[4];
        {
            const uint4* b = (const uint4*)g_w1pk;
#pragma unroll
            for (int i = 0; i < 4; i++) cb[i] = b[i * 128 + tid];
        }

        // ---- build A (raw), two 16-row chunks; pack fp16 frags (12 ks) -----
#pragma unroll 1
        for (int half = 0; half < 2; half++) {
            const int base = g0 + half * 16;
            float* rawH = rawS + half * 16 * 60;
            if (base + 16 <= n) {
                const float4* sem4 = (const float4*)p.sem;
                const float4* shs4 = (const float4*)p.shs;
#pragma unroll 1
                for (int i = tid; i < 512; i += 128) {       // sem: 16 x 128
                    int r = i & 15, c = i >> 4;
                    float4 v = sem4[(base + r) * 32 + c];
                    float* d = H1raw + r * 257 + 59 + c * 4;
                    d[0] = v.x; d[1] = v.y; d[2] = v.z; d[3] = v.w;
                }
#pragma unroll 1
                for (int i = tid; i < 192; i += 128) {       // shs (+rawS)
                    int r = i & 15, c = i >> 4;
                    float4 v = shs4[(base + r) * 12 + c];
                    float* d = H1raw + r * 257 + 11 + c * 4;
                    d[0] = v.x; d[1] = v.y; d[2] = v.z; d[3] = v.w;
                    float* rw = rawH + r * 60 + 10 + c * 4;
                    rw[0] = v.x; rw[1] = v.y; rw[2] = v.z; rw[3] = v.w;
                }
#pragma unroll 1
                for (int i = tid; i < 208; i += 128) {       // pnt/rot/scl/dx
                    int r = i & 15, j = i >> 4;
                    int g = base + r;
                    float v;
                    if (j < 3)       v = p.pnt[g * 3 + j];
                    else if (j < 7)  v = p.rot[g * 4 + j - 3];
                    else if (j < 10) v = p.scl[g * 3 + j - 7];
                    else             v = p.dx[g * 3 + j - 10];
                    if (j < 10) {
                        H1raw[r * 257 + j] = v;
                        rawH[r * 60 + j] = v;
                    } else {
                        H1raw[r * 257 + 177 + j] = v;        // cols 187..189
                    }
                }
                if (tid < 16) {
                    int g = base + tid;
                    H1raw[tid * 257 + 10]  = p.opa[g];
                    H1raw[tid * 257 + 190] = p.tim[g];
                    H1raw[tid * 257 + 191] = 0.0f;           // pad col
                }
            } else {
                for (int idx = tid; idx < 16 * 192; idx += 128) {
                    int lr = idx / 192, k = idx % 192;
                    int g = base + lr;
                    float v = 0.0f;
                    if (g < n && k < 191) {
                        if      (k < 3)    v = p.pnt[g * 3 + k];
                        else if (k < 7)    v = p.rot[g * 4 + (k - 3)];
                        else if (k < 10)   v = p.scl[g * 3 + (k - 7)];
                        else if (k == 10)  v = p.opa[g];
                        else if (k < 59)   v = p.shs[g * 48 + (k - 11)];
                        else if (k < 187)  v = p.sem[g * 128 + (k - 59)];
                        else if (k < 190)  v = p.dx[g * 3 + (k - 187)];
                        else               v = p.tim[g];
                    }
                    H1raw[lr * 257 + k] = v;
                    if (k < 10) rawH[lr * 60 + k] = v;
                    else if (k >= 11 && k < 59) rawH[lr * 60 + k - 1] = v;
                }
            }
            __syncthreads();
#pragma unroll 1
            for (int j = 0; j < 3; j++) {
                int ks = w * 3 + j;
                int r0 = gq, r1 = gq + 8;
                int k0 = ks * 16 + cc * 2;
                uint4 fr;
                fr.x = f2h2(fmaxf(H1raw[r0 * 257 + k0],     0.0f),
                            fmaxf(H1raw[r0 * 257 + k0 + 1], 0.0f));
                fr.y = f2h2(fmaxf(H1raw[r1 * 257 + k0],     0.0f),
                            fmaxf(H1raw[r1 * 257 + k0 + 1], 0.0f));
                fr.z = f2h2(fmaxf(H1raw[r0 * 257 + k0 + 8], 0.0f),
                            fmaxf(H1raw[r0 * 257 + k0 + 9], 0.0f));
                fr.w = f2h2(fmaxf(H1raw[r1 * 257 + k0 + 8], 0.0f),
                            fmaxf(H1raw[r1 * 257 + k0 + 9], 0.0f));
                *(uint4*)(sm + OFF_APK + apk1(ks, half, lane)) = fr;
            }
            __syncthreads();
        }
        if (tid < 32) { int g = g0 + tid; if (g < n) p.out[10 * n + g] = p.opa[g]; }

#pragma unroll 1
        for (int h = 0; h < 5; h++) {
            float acc[2][8][4];
#pragma unroll
            for (int a = 0; a < 2; a++)
#pragma unroll
                for (int b = 0; b < 8; b++)
#pragma unroll
                    for (int e = 0; e < 4; e++) acc[a][b][e] = 0.0f;

            // ------- GEMM1 mainloop: K=192 (12 ks), unrolled x2 ping-pong ----
            const unsigned char* hbase = g_w1pk + (size_t)(h * 12) * 8192;
#pragma unroll 1
            for (int ks = 0; ks < 12; ks += 2) {
                uint4 nb[4];
                {
                    const uint4* b = (const uint4*)(hbase + (size_t)(ks + 1) * 8192);
#pragma unroll
                    for (int i = 0; i < 4; i++) nb[i] = b[i * 128 + tid];
                }
                MMA_BLOCK(cb, ks);
                if (ks < 10) {
                    const uint4* b = (const uint4*)(hbase + (size_t)(ks + 2) * 8192);
#pragma unroll
                    for (int i = 0; i < 4; i++) cb[i] = b[i * 128 + tid];
                } else if (h < 4) {
                    const uint4* b = (const uint4*)(g_w1pk + (size_t)((h + 1) * 12) * 8192);
#pragma unroll
                    for (int i = 0; i < 4; i++) cb[i] = b[i * 128 + tid];
                }
                MMA_BLOCK(nb, ks + 1);
            }

            // combined bias bc = b1 + cvec(tpe), this warp's n-slice
            float b1r[16];
#pragma unroll
            for (int nt = 0; nt < 8; nt++)
#pragma unroll
                for (int e = 0; e < 2; e++) {
                    int nn = w * 64 + nt * 8 + cc * 2 + e;
                    b1r[nt * 2 + e] = g_bc[h][nn];
                }

            if (h < 4) {
                // ------- GEMM2 partials IN-REGISTER (C-frag == A-frag) -------
                float d[2][4] = {{0, 0, 0, 0}, {0, 0, 0, 0}};
                const uint2* wb = (const uint2*)g_w2pk + h * 16 * 32;
#pragma unroll
                for (int j = 0; j < 4; j++) {
                    uint2 B = wb[(4 * w + j) * 32 + lane];
#pragma unroll
                    for (int mt = 0; mt < 2; mt++) {
                        uint32_t A[4];
                        A[0] = f2h2(fmaxf(acc[mt][2 * j][0] + b1r[4 * j + 0], 0.0f),
                                    fmaxf(acc[mt][2 * j][1] + b1r[4 * j + 1], 0.0f));
                        A[1] = f2h2(fmaxf(acc[mt][2 * j][2] + b1r[4 * j + 0], 0.0f),
                                    fmaxf(acc[mt][2 * j][3] + b1r[4 * j + 1], 0.0f));
                        A[2] = f2h2(fmaxf(acc[mt][2 * j + 1][0] + b1r[4 * j + 2], 0.0f),
                                    fmaxf(acc[mt][2 * j + 1][1] + b1r[4 * j + 3], 0.0f));
                        A[3] = f2h2(fmaxf(acc[mt][2 * j + 1][2] + b1r[4 * j + 2], 0.0f),
                                    fmaxf(acc[mt][2 * j + 1][3] + b1r[4 * j + 3], 0.0f));
                        mma_f16(d[mt], A, B.x, B.y);
                    }
                }
                float4* redh = (float4*)(sm + OFF_SCR + h * 4096);
#pragma unroll
                for (int mt = 0; mt < 2; mt++)
                    redh[w * 64 + mt * 32 + lane] =
                        make_float4(d[mt][0], d[mt][1], d[mt][2], d[mt][3]);
            } else {
                // ------- head 4: pack H1 fp16 frags (16 ks) into APK ---------
                __syncthreads();   // A frags dead; red writes done
#pragma unroll
                for (int j = 0; j < 4; j++) {
                    const int ks2 = 4 * w + j;
#pragma unroll
                    for (int mt = 0; mt < 2; mt++) {
                        uint4 fr;
                        fr.x = f2h2(fmaxf(acc[mt][2 * j][0] + b1r[4 * j + 0], 0.0f),
                                    fmaxf(acc[mt][2 * j][1] + b1r[4 * j + 1], 0.0f));
                        fr.y = f2h2(fmaxf(acc[mt][2 * j][2] + b1r[4 * j + 0], 0.0f),
                                    fmaxf(acc[mt][2 * j][3] + b1r[4 * j + 1], 0.0f));
                        fr.z = f2h2(fmaxf(acc[mt][2 * j + 1][0] + b1r[4 * j + 2], 0.0f),
                                    fmaxf(acc[mt][2 * j + 1][1] + b1r[4 * j + 3], 0.0f));
                        fr.w = f2h2(fmaxf(acc[mt][2 * j + 1][2] + b1r[4 * j + 2], 0.0f),
                                    fmaxf(acc[mt][2 * j + 1][3] + b1r[4 * j + 3], 0.0f));
                        *(uint4*)(sm + OFF_APK + apk1(ks2, mt, lane)) = fr;
                    }
                }
                __syncthreads();   // H1pk + all red[h] visible

                // ------- combined: reduce heads 0-3 (warp = head) + mask -----
                {
                    const int hh = w;
                    const float4* redb = (const float4*)(sm + OFF_SCR);
                    float ds[2][4];
#pragma unroll
                    for (int mt = 0; mt < 2; mt++) {
                        float4 a4 = make_float4(0.f, 0.f, 0.f, 0.f);
#pragma unroll
                        for (int wi = 0; wi < 4; wi++) {
                            float4 r = redb[hh * 256 + wi * 64 + mt * 32 + lane];
                            a4.x += r.x; a4.y += r.y; a4.z += r.z; a4.w += r.w;
                        }
                        ds[mt][0] = a4.x; ds[mt][1] = a4.y;
                        ds[mt][2] = a4.z; ds[mt][3] = a4.w;
                    }
                    if (hh == 0 && cc == 0) {
                        float b20 = p.b2[0][0];
#pragma unroll
                        for (int mt = 0; mt < 2; mt++) {
                            maskS[mt * 16 + gq]     = 1.0f / (1.0f + expf(-(ds[mt][0] + b20)));
                            maskS[mt * 16 + gq + 8] = 1.0f / (1.0f + expf(-(ds[mt][2] + b20)));
                        }
                    }
                    __syncthreads();    // maskS visible
                    if (hh >= 1) {
                        const int od = (hh == 3) ? 4 : 3;
#pragma unroll
                        for (int mt = 0; mt < 2; mt++)
#pragma unroll
                            for (int e = 0; e < 4; e++) {
                                int o = cc * 2 + (e & 1);
                                if (o < od) {
                                    int m = mt * 16 + gq + ((e >> 1) << 3);
                                    int g = g0 + m;
                                    if (g < n) {
                                        float val = ds[mt][e] + p.b2[hh][o];
                                        float mk = maskS[m];
                                        if (hh == 1) {
                                            p.out[59 * n + g * 3 + o] = val;
                                            p.out[g * 3 + o] = rawS[m * 60 + o] + val * mk;
                                        } else if (hh == 2) {
                                            p.out[3 * n + g * 3 + o] =
                                                rawS[m * 60 + 7 + o] + val * mk;
                                        } else {
                                            p.out[6 * n + g * 4 + o] =
                                                rawS[m * 60 + 3 + o] + val * mk;
                                        }
                                    }
                                }
                            }
                    }
                }

                // ------- head 4 GEMM2 on HMMA: 12 jobs over 4 warps ----------
#pragma unroll 1
                for (int jb = 0; jb < 3; jb++) {
                    int t = w + 4 * jb;            // 0..11
                    int mt = t / 6, nt2 = t % 6;
                    float d0[4] = {0, 0, 0, 0};
                    const uint2* wb = (const uint2*)g_w2pk + (4 + nt2) * 16 * 32;
                    uint2 B = wb[lane];
#pragma unroll 1
                    for (int ks2 = 0; ks2 < 16; ks2++) {
                        uint2 Bn;
                        if (ks2 < 15) Bn = wb[(ks2 + 1) * 32 + lane];
                        uint4 ah4 = *(const uint4*)(sm + OFF_APK + apk1(ks2, mt, lane));
                        uint32_t ah[4] = {ah4.x, ah4.y, ah4.z, ah4.w};
                        mma_f16(d0, ah, B.x, B.y);
                        if (ks2 < 15) B = Bn;
                    }
#pragma unroll
                    for (int e = 0; e < 4; e++) {
                        int o = nt2 * 8 + cc * 2 + (e & 1);
                        int m = mt * 16 + gq + ((e >> 1) << 3);
                        int g = g0 + m;
                        if (g < n) {
                            float val = d0[e] + p.b2[4][o];
                            float mk = maskS[m];
                            p.out[oDSH + g * 48 + o] = val;
                            p.out[oSHS + g * 48 + o] = rawS[m * 60 + 10 + o] + val * mk;
                        }
                    }
                }
            }
        }
    }
}

extern "C" void kernel_launch(void* const* d_in, const int* in_sizes, int n_in,
                              void* d_out, int out_size) {
    Params p;
    p.opa = (const float*)d_in[0];
    p.shs = (const float*)d_in[1];
    p.tim = (const float*)d_in[2];
    p.sem = (const float*)d_in[3];
    p.pnt = (const float*)d_in[4];
    p.scl = (const float*)d_in[5];
    p.rot = (const float*)d_in[6];
    p.dx  = (const float*)d_in[7];
    for (int h = 0; h < 5; h++) {
        p.w1[h] = (const float*)d_in[8 + h * 4 + 0];
        p.b1[h] = (const float*)d_in[8 + h * 4 + 1];
        p.w2[h] = (const float*)d_in[8 + h * 4 + 2];
        p.b2[h] = (const float*)d_in[8 + h * 4 + 3];
    }
    p.out    = (float*)d_out;
    p.n      = in_sizes[0];
    p.ntiles = (p.n + 31) / 32;

    prep_all<<<180, 256>>>(p.w1[0], p.w1[1], p.w1[2], p.w1[3], p.w1[4],
                           p.w2[0], p.w2[1], p.w2[2], p.w2[3], p.w2[4],
                           p.b1[0], p.b1[1], p.b1[2], p.b1[3], p.b1[4],
                           p.tim);

    cudaFuncSetAttribute(deform13, cudaFuncAttributeMaxDynamicSharedMemorySize, SMEM_BYTES);
    int grid = 4 * 148;
    if (grid > p.ntiles) grid = p.ntiles;
    deform13<<<grid, 128, SMEM_BYTES>>>(p);
}